// round 6
// baseline (speedup 1.0000x reference)
#include <cuda_runtime.h>
#include <cuda_bf16.h>
#include <cstdint>
#include <math.h>

// ---------------- problem dims ----------------
#define BATCH 2048
#define TLEN  80
#define EDIM  100
#define UNITS 512
#define DPAD  128              // embedding K padded 100 -> 128
#define KC    64               // K chunk (64 bf16 = 128 B row)
#define NCH   8                // H chunks (K = 512)
#define BM    128
#define BN    64
#define NCTA  128
#define GRPSZ 8

// ---------------- static device scratch ----------------
__device__ __nv_bfloat16 g_Hhi[2][BATCH * UNITS];
__device__ __nv_bfloat16 g_Hlo[2][BATCH * UNITS];
__device__ __nv_bfloat16 g_Wbhi[UNITS * UNITS];   // W_hh planes, [n][k]
__device__ __nv_bfloat16 g_Wblo[UNITS * UNITS];
__device__ __nv_bfloat16 g_WXhi[UNITS * DPAD];    // W_xh planes, [n][k], k padded
__device__ __nv_bfloat16 g_WXlo[UNITS * DPAD];
__device__ float g_XW[(size_t)TLEN * BATCH * UNITS];   // x@W_xh + b_h
__device__ unsigned g_flag[NCTA * 32];            // per (grp, col) flags, 128B stride

// ---------------- PTX helpers ----------------
__device__ __forceinline__ uint32_t smem_to_u32(const void* p) {
    uint32_t a;
    asm("{ .reg .u64 t; cvta.to.shared.u64 t, %1; cvt.u32.u64 %0, t; }" : "=r"(a) : "l"(p));
    return a;
}
#define CP16(dst, src) \
    asm volatile("cp.async.cg.shared.global [%0], [%1], 16;" :: "r"(dst), "l"(src))
#define CP_COMMIT() asm volatile("cp.async.commit_group;" ::: "memory")
#define CP_WAIT(n)  asm volatile("cp.async.wait_group %0;" :: "n"(n) : "memory")

#define LDSM_X4(r0, r1, r2, r3, addr) \
    asm volatile("ldmatrix.sync.aligned.m8n8.x4.shared.b16 {%0,%1,%2,%3}, [%4];" \
                 : "=r"(r0), "=r"(r1), "=r"(r2), "=r"(r3) : "r"(addr))

#define MMA16816(d, a0, a1, a2, a3, b0, b1) \
    asm volatile("mma.sync.aligned.m16n8k16.row.col.f32.bf16.bf16.f32 " \
                 "{%0,%1,%2,%3}, {%4,%5,%6,%7}, {%8,%9}, {%0,%1,%2,%3};" \
                 : "+f"((d)[0]), "+f"((d)[1]), "+f"((d)[2]), "+f"((d)[3]) \
                 : "r"(a0), "r"(a1), "r"(a2), "r"(a3), "r"(b0), "r"(b1))

#define SWZ(bo) ((bo) ^ (((bo) >> 3) & 0x70))

// ---------------- SMEM layouts ----------------
// main kernel: B resident 8 chunks x 2 planes x 8KB = 128KB; A 3 bufs x 2 planes x 16KB = 96KB
#define B_RES(p, c)   ((p) * 65536 + (c) * 8192)
#define A_OFF(buf, p) (131072 + ((buf) * 2 + (p)) * 16384)
#define SMEM_MAIN     229376
// xw kernel: A 2 planes x 2 chunks x 16KB = 64KB; B 2 planes x 2 chunks x 8KB = 32KB; bias 256B
#define XA(p, ch) (((p) * 2 + (ch)) * 16384)
#define XB(p, ch) (65536 + ((p) * 2 + (ch)) * 8192)
#define XBIAS     98304
#define SMEM_XW   98560

// ---------------- prep kernels ----------------
__global__ void build_whh_kernel(const float* __restrict__ Whh) {
    int i = blockIdx.x * blockDim.x + threadIdx.x;
    if (i >= UNITS * UNITS) return;
    int n = i / UNITS;
    int k = i - n * UNITS;
    float v = Whh[(size_t)k * UNITS + n];
    __nv_bfloat16 hi = __float2bfloat16(v);
    g_Wbhi[i] = hi;
    g_Wblo[i] = __float2bfloat16(v - __bfloat162float(hi));
}

__global__ void build_wxh_kernel(const float* __restrict__ Wxh) {
    int i = blockIdx.x * blockDim.x + threadIdx.x;
    if (i >= UNITS * DPAD) return;
    int n = i / DPAD;
    int k = i - n * DPAD;
    float v = (k < EDIM) ? Wxh[(size_t)k * UNITS + n] : 0.0f;
    __nv_bfloat16 hi = __float2bfloat16(v);
    g_WXhi[i] = hi;
    g_WXlo[i] = __float2bfloat16(v - __bfloat162float(hi));
}

__global__ void init_h_kernel() {
    int i = blockIdx.x * blockDim.x + threadIdx.x;
    if (i < NCTA * 32) g_flag[i] = 0u;
    if (i >= BATCH * UNITS) return;
    g_Hhi[0][i] = __float2bfloat16(0.0f);
    g_Hlo[0][i] = __float2bfloat16(0.0f);
}

// ---------------- xw precompute: g_XW = gather(emb) @ W_xh + b_h ----------------
// grid (8, 1280), 256 threads, warp tile 32M x 32N.
__global__ __launch_bounds__(256, 2)
void xw_gemm(const int* __restrict__ inputs, const float* __restrict__ emb,
             const float* __restrict__ bh) {
    extern __shared__ char smem[];
    const uint32_t su = smem_to_u32(smem);
    const int tid = threadIdx.x, wid = tid >> 5, lane = tid & 31;
    const int col0 = blockIdx.x * BN;
    const int r0   = blockIdx.y * BM;      // global row in [0, T*B)

    // zero A planes (covers the k in [100,128) padding)
    {
        uint4 z = make_uint4(0, 0, 0, 0);
#pragma unroll
        for (int i = 0; i < 16; i++)
            *reinterpret_cast<uint4*>(smem + tid * 16 + i * 4096) = z;
    }
    // B planes (W_xh) via cp.async
    {
        const __nv_bfloat16* w0 = g_WXhi + (size_t)col0 * DPAD;
        const __nv_bfloat16* w1 = g_WXlo + (size_t)col0 * DPAD;
#pragma unroll
        for (int i = 0; i < 4; i++) {
            int u = tid + i * 256;           // 0..1023
            int rg = u >> 3, s = u & 7;
            int ch = rg >> 6, r = rg & 63;
            uint32_t so = SWZ((uint32_t)(r * 128 + s * 16));
            size_t gs = (size_t)r * DPAD + ch * 64;
            CP16(su + XB(0, ch) + so, (const char*)(w0 + gs) + s * 16);
            CP16(su + XB(1, ch) + so, (const char*)(w1 + gs) + s * 16);
        }
    }
    if (tid < 64) reinterpret_cast<float*>(smem + XBIAS)[tid] = bh[col0 + tid];
    CP_COMMIT();
    __syncthreads();   // zero-fill visible before gather writes

    // gather + hi/lo split into A planes (2 threads per row)
    {
        const int row = tid >> 1, sub = tid & 1;
        const int gr = r0 + row;
        const int t = gr >> 11;              // / 2048
        const int b = gr & 2047;
        const int idx = inputs[(size_t)b * TLEN + t];
        const float4* src = reinterpret_cast<const float4*>(emb + (size_t)idx * EDIM);
#pragma unroll
        for (int f4 = sub; f4 < 25; f4 += 2) {
            float4 v = src[f4];
            int k = f4 * 4;
            int ch = k >> 6, kk = k & 63;
            uint32_t so = SWZ((uint32_t)(row * 128 + kk * 2));
            __nv_bfloat162 hp0, hp1, lp0, lp1;
            hp0.x = __float2bfloat16(v.x); hp0.y = __float2bfloat16(v.y);
            hp1.x = __float2bfloat16(v.z); hp1.y = __float2bfloat16(v.w);
            lp0.x = __float2bfloat16(v.x - __bfloat162float(hp0.x));
            lp0.y = __float2bfloat16(v.y - __bfloat162float(hp0.y));
            lp1.x = __float2bfloat16(v.z - __bfloat162float(hp1.x));
            lp1.y = __float2bfloat16(v.w - __bfloat162float(hp1.y));
            *reinterpret_cast<__nv_bfloat162*>(smem + XA(0, ch) + so)     = hp0;
            *reinterpret_cast<__nv_bfloat162*>(smem + XA(0, ch) + so + 4) = hp1;
            *reinterpret_cast<__nv_bfloat162*>(smem + XA(1, ch) + so)     = lp0;
            *reinterpret_cast<__nv_bfloat162*>(smem + XA(1, ch) + so + 4) = lp1;
        }
    }
    CP_WAIT(0);
    __syncthreads();

    // warp tiling: 4 warps M x 2 warps N; warp tile 32 x 32
    const int m_base = (wid & 3) * 32;
    const int n_base = (wid >> 2) * 32;
    const int a_row = lane & 15, a_kh = (lane >> 4) * 16;
    const int b_row = ((lane >> 4) << 3) + (lane & 7), b_kh = ((lane >> 3) & 1) * 16;
    const int g = lane >> 2, tig = lane & 3;

    float acc[2][4][4];
    const float* sbias = reinterpret_cast<const float*>(smem + XBIAS);
#pragma unroll
    for (int mt = 0; mt < 2; mt++)
#pragma unroll
        for (int nt = 0; nt < 4; nt++) {
            float b0 = sbias[n_base + nt * 8 + tig * 2];
            float b1 = sbias[n_base + nt * 8 + tig * 2 + 1];
            acc[mt][nt][0] = b0; acc[mt][nt][1] = b1;
            acc[mt][nt][2] = b0; acc[mt][nt][3] = b1;
        }

    // K = 112 effective (k in [100,112) zero, [112,128) skipped): 7 k-steps
#pragma unroll
    for (int kstep = 0; kstep < 7; kstep++) {
        const int ch = kstep >> 2;
        const int kb = (kstep & 3) * 32;
        uint32_t Ah[2][4], Al[2][4], Bh[4][2], Bl[4][2];
#pragma unroll
        for (int mt = 0; mt < 2; mt++) {
            uint32_t bo = SWZ((uint32_t)((m_base + mt * 16 + a_row) * 128 + kb + a_kh));
            LDSM_X4(Ah[mt][0], Ah[mt][1], Ah[mt][2], Ah[mt][3], su + XA(0, ch) + bo);
            LDSM_X4(Al[mt][0], Al[mt][1], Al[mt][2], Al[mt][3], su + XA(1, ch) + bo);
        }
#pragma unroll
        for (int np = 0; np < 2; np++) {
            uint32_t bo = SWZ((uint32_t)((n_base + np * 16 + b_row) * 128 + kb + b_kh));
            LDSM_X4(Bh[np * 2][0], Bh[np * 2][1], Bh[np * 2 + 1][0], Bh[np * 2 + 1][1],
                    su + XB(0, ch) + bo);
            LDSM_X4(Bl[np * 2][0], Bl[np * 2][1], Bl[np * 2 + 1][0], Bl[np * 2 + 1][1],
                    su + XB(1, ch) + bo);
        }
#pragma unroll
        for (int mt = 0; mt < 2; mt++)
#pragma unroll
            for (int nt = 0; nt < 4; nt++) {
                MMA16816(acc[mt][nt], Ah[mt][0], Ah[mt][1], Ah[mt][2], Ah[mt][3],
                         Bh[nt][0], Bh[nt][1]);
                MMA16816(acc[mt][nt], Ah[mt][0], Ah[mt][1], Ah[mt][2], Ah[mt][3],
                         Bl[nt][0], Bl[nt][1]);
                MMA16816(acc[mt][nt], Al[mt][0], Al[mt][1], Al[mt][2], Al[mt][3],
                         Bh[nt][0], Bh[nt][1]);
            }
    }

    // store fp32
    float* dst = g_XW + (size_t)r0 * UNITS;
#pragma unroll
    for (int mt = 0; mt < 2; mt++)
#pragma unroll
        for (int nt = 0; nt < 4; nt++) {
            const int col = col0 + n_base + nt * 8 + tig * 2;
#pragma unroll
            for (int half = 0; half < 2; half++) {
                const int row = m_base + mt * 16 + g + half * 8;
                float2 v; v.x = acc[mt][nt][half * 2]; v.y = acc[mt][nt][half * 2 + 1];
                *reinterpret_cast<float2*>(dst + (size_t)row * UNITS + col) = v;
            }
        }
}

// ---------------- persistent recurrence (K = 512) ----------------
__global__ __launch_bounds__(512, 1)
void rnn_persistent() {
    extern __shared__ char smem[];
    const uint32_t su = smem_to_u32(smem);
    const int tid = threadIdx.x, wid = tid >> 5, lane = tid & 31;
    const int bid = blockIdx.x;
    const int cidx = bid & 7;
    const int grp  = bid >> 3;
    const int col0 = cidx * BN, row0 = grp * BM;

    // resident B: W_hh planes, 8 chunks
    {
        const __nv_bfloat16* w0 = g_Wbhi + (size_t)col0 * UNITS;
        const __nv_bfloat16* w1 = g_Wblo + (size_t)col0 * UNITS;
#pragma unroll
        for (int i = 0; i < 8; i++) {
            int u = tid + i * 512;           // 0..4095 per plane
            int rg = u >> 3, s = u & 7;
            int ch = rg >> 6, r = rg & 63;
            uint32_t so = SWZ((uint32_t)(r * 128 + s * 16));
            size_t gs = (size_t)r * UNITS + ch * 64;
            CP16(su + B_RES(0, ch) + so, (const char*)(w0 + gs) + s * 16);
            CP16(su + B_RES(1, ch) + so, (const char*)(w1 + gs) + s * 16);
        }
    }
    CP_COMMIT();
    CP_WAIT(0);
    __syncthreads();

    const int m_base = (wid & 3) * 32;
    const int n_base = (wid >> 2) * 16;
    const int a_row = lane & 15, a_kh = (lane >> 4) * 16;
    const int b_row = ((lane >> 4) << 3) + (lane & 7), b_kh = ((lane >> 3) & 1) * 16;
    const int g = lane >> 2, tig = lane & 3;

    for (int t = 0; t < TLEN; t++) {
        const __nv_bfloat16* __restrict__ Hh = g_Hhi[t & 1];
        const __nv_bfloat16* __restrict__ Hl = g_Hlo[t & 1];

        // acc init = xw slice (bias already folded)
        float acc[2][2][4];
        {
            const float* xw = g_XW + ((size_t)t * BATCH + row0) * UNITS;
#pragma unroll
            for (int mt = 0; mt < 2; mt++)
#pragma unroll
                for (int nt = 0; nt < 2; nt++) {
                    const int col = col0 + n_base + nt * 8 + tig * 2;
#pragma unroll
                    for (int half = 0; half < 2; half++) {
                        const int row = m_base + mt * 16 + g + half * 8;
                        float2 v = __ldg(reinterpret_cast<const float2*>(
                                             xw + (size_t)row * UNITS + col));
                        acc[mt][nt][half * 2] = v.x;
                        acc[mt][nt][half * 2 + 1] = v.y;
                    }
                }
        }

        auto spin = [&](int kc) {
            const unsigned* fp = &g_flag[(grp * 8 + kc) * 32];
            unsigned v;
            do {
                asm volatile("ld.acquire.gpu.u32 %0, [%1];" : "=r"(v) : "l"(fp));
            } while ((int)v < t);
        };
        auto load_A = [&](int kc, int buf) {
            const __nv_bfloat16* sh = Hh + (size_t)row0 * UNITS + kc * KC;
            const __nv_bfloat16* sl = Hl + (size_t)row0 * UNITS + kc * KC;
#pragma unroll
            for (int i = 0; i < 2; i++) {
                int u = tid + i * 512;
                int r = u >> 3, s = u & 7;
                uint32_t so = SWZ((uint32_t)(r * 128 + s * 16));
                CP16(su + A_OFF(buf, 0) + so, (const char*)(sh + (size_t)r * UNITS) + s * 16);
                CP16(su + A_OFF(buf, 1) + so, (const char*)(sl + (size_t)r * UNITS) + s * 16);
            }
            CP_COMMIT();
        };

        // staggered chunk order: start with own column's tile (always ready)
        {
            int k0 = cidx;          spin(k0); load_A(k0, 0);
            int k1 = (cidx + 1) & 7; spin(k1); load_A(k1, 1);
        }

        uint32_t Ah[2][2][4], Al[2][2][4], Bhf[2][2][2], Blf[2][2][2];

        for (int ci = 0; ci < NCH; ci++) {
            const int kc = (cidx + ci) & 7;
            const int buf = ci % 3;
            if (ci < NCH - 1) { CP_WAIT(1); } else { CP_WAIT(0); }
            __syncthreads();

            const uint32_t ah  = su + A_OFF(buf, 0);
            const uint32_t al  = su + A_OFF(buf, 1);
            const uint32_t bhp = su + B_RES(0, kc);
            const uint32_t blp = su + B_RES(1, kc);

#define LDSM_KS(pb, ks) do {                                                      \
                const int kb_ = (ks) * 32;                                        \
                _Pragma("unroll")                                                 \
                for (int mt = 0; mt < 2; mt++) {                                  \
                    uint32_t bo = SWZ((uint32_t)((m_base + mt * 16 + a_row) * 128 \
                                                 + kb_ + a_kh));                  \
                    LDSM_X4(Ah[pb][mt][0], Ah[pb][mt][1],                         \
                            Ah[pb][mt][2], Ah[pb][mt][3], ah + bo);               \
                    LDSM_X4(Al[pb][mt][0], Al[pb][mt][1],                         \
                            Al[pb][mt][2], Al[pb][mt][3], al + bo);               \
                }                                                                 \
                uint32_t bo2 = SWZ((uint32_t)((n_base + b_row) * 128              \
                                              + kb_ + b_kh));                     \
                LDSM_X4(Bhf[pb][0][0], Bhf[pb][0][1],                             \
                        Bhf[pb][1][0], Bhf[pb][1][1], bhp + bo2);                 \
                LDSM_X4(Blf[pb][0][0], Blf[pb][0][1],                             \
                        Blf[pb][1][0], Blf[pb][1][1], blp + bo2);                 \
            } while (0)

#define MMA_KS(pb) do {                                                           \
                _Pragma("unroll")                                                 \
                for (int mt = 0; mt < 2; mt++) {                                  \
                    _Pragma("unroll")                                             \
                    for (int nt = 0; nt < 2; nt++) {                              \
                        MMA16816(acc[mt][nt], Ah[pb][mt][0], Ah[pb][mt][1],       \
                                 Ah[pb][mt][2], Ah[pb][mt][3],                    \
                                 Bhf[pb][nt][0], Bhf[pb][nt][1]);                 \
                        MMA16816(acc[mt][nt], Ah[pb][mt][0], Ah[pb][mt][1],       \
                                 Ah[pb][mt][2], Ah[pb][mt][3],                    \
                                 Blf[pb][nt][0], Blf[pb][nt][1]);                 \
                        MMA16816(acc[mt][nt], Al[pb][mt][0], Al[pb][mt][1],       \
                                 Al[pb][mt][2], Al[pb][mt][3],                    \
                                 Bhf[pb][nt][0], Bhf[pb][nt][1]);                 \
                    }                                                             \
                }                                                                 \
            } while (0)

            LDSM_KS(0, 0);
            LDSM_KS(1, 1);
            MMA_KS(0);
            LDSM_KS(0, 2);
            MMA_KS(1);
            LDSM_KS(1, 3);
            MMA_KS(0);
            MMA_KS(1);

            // prefetch 2 ahead (triple buffer: target != any buffer in use)
            if (ci + 2 < NCH) {
                int kn = (cidx + ci + 2) & 7;
                spin(kn);
                load_A(kn, (ci + 2) % 3);
            }
        }

        // ---- epilogue: tanh, hi/lo split, store ----
        __nv_bfloat16* __restrict__ dhP = g_Hhi[(t + 1) & 1];
        __nv_bfloat16* __restrict__ dlP = g_Hlo[(t + 1) & 1];
#pragma unroll
        for (int mt = 0; mt < 2; mt++) {
#pragma unroll
            for (int nt = 0; nt < 2; nt++) {
                const int col = col0 + n_base + nt * 8 + tig * 2;
#pragma unroll
                for (int half = 0; half < 2; half++) {
                    const int row = row0 + m_base + mt * 16 + g + half * 8;
                    float v0 = tanhf(acc[mt][nt][half * 2 + 0]);
                    float v1 = tanhf(acc[mt][nt][half * 2 + 1]);
                    __nv_bfloat16 h0 = __float2bfloat16(v0);
                    __nv_bfloat16 h1 = __float2bfloat16(v1);
                    __nv_bfloat16 l0 = __float2bfloat16(v0 - __bfloat162float(h0));
                    __nv_bfloat16 l1 = __float2bfloat16(v1 - __bfloat162float(h1));
                    __nv_bfloat162 hp; hp.x = h0; hp.y = h1;
                    __nv_bfloat162 lp; lp.x = l0; lp.y = l1;
                    *reinterpret_cast<__nv_bfloat162*>(dhP + (size_t)row * UNITS + col) = hp;
                    *reinterpret_cast<__nv_bfloat162*>(dlP + (size_t)row * UNITS + col) = lp;
                }
            }
        }

        // ---- release flag: H_{t+1} tile (grp, cidx) available ----
        __threadfence();
        __syncthreads();
        if (tid == 0) {
            unsigned* fp = &g_flag[(grp * 8 + cidx) * 32];
            asm volatile("st.release.gpu.u32 [%0], %1;"
                         :: "l"(fp), "r"((unsigned)(t + 1)) : "memory");
        }
    }
}

// ---------------- final logits ----------------
__global__ __launch_bounds__(256)
void final_logits_kernel(const float* __restrict__ Wout,
                         const float* __restrict__ bout,
                         float* __restrict__ out) {
    const __nv_bfloat16* __restrict__ hh = g_Hhi[0];  // TLEN = 80 even -> plane 0
    const __nv_bfloat16* __restrict__ hl = g_Hlo[0];
    int warp = threadIdx.x >> 5;
    int lane = threadIdx.x & 31;
    int row = blockIdx.x * 8 + warp;
    if (row >= BATCH) return;
    float s = 0.0f;
#pragma unroll
    for (int j = 0; j < UNITS / 32; j++) {
        int k = lane + j * 32;
        float h = __bfloat162float(hh[(size_t)row * UNITS + k]) +
                  __bfloat162float(hl[(size_t)row * UNITS + k]);
        s += h * Wout[k];
    }
#pragma unroll
    for (int o = 16; o; o >>= 1) s += __shfl_xor_sync(0xffffffff, s, o);
    if (lane == 0) out[row] = 1.0f / (1.0f + expf(-(s + bout[0])));
}

// ---------------- launch ----------------
extern "C" void kernel_launch(void* const* d_in, const int* in_sizes, int n_in,
                              void* d_out, int out_size) {
    const int*   inputs = (const int*)  d_in[0];
    const float* emb    = (const float*)d_in[1];
    const float* Wxh    = (const float*)d_in[2];
    const float* Whh    = (const float*)d_in[3];
    const float* bh     = (const float*)d_in[4];
    const float* Wout   = (const float*)d_in[5];
    const float* bout   = (const float*)d_in[6];
    float* out = (float*)d_out;

    cudaFuncSetAttribute(rnn_persistent,
                         cudaFuncAttributeMaxDynamicSharedMemorySize, SMEM_MAIN);
    cudaFuncSetAttribute(xw_gemm,
                         cudaFuncAttributeMaxDynamicSharedMemorySize, SMEM_XW);

    build_whh_kernel<<<(UNITS * UNITS + 255) / 256, 256>>>(Whh);
    build_wxh_kernel<<<(UNITS * DPAD + 255) / 256, 256>>>(Wxh);
    init_h_kernel<<<(BATCH * UNITS + 255) / 256, 256>>>();

    dim3 gx(UNITS / BN, (TLEN * BATCH) / BM);   // (8, 1280)
    xw_gemm<<<gx, 256, SMEM_XW>>>(inputs, emb, bh);

    rnn_persistent<<<NCTA, 512, SMEM_MAIN>>>();

    final_logits_kernel<<<BATCH / 8, 256>>>(Wout, bout, out);
}

// round 7
// speedup vs baseline: 1.5292x; 1.5292x over previous
#include <cuda_runtime.h>
#include <cuda_fp16.h>
#include <cstdint>
#include <math.h>

// ---------------- problem dims ----------------
#define BATCH 2048
#define TLEN  80
#define EDIM  100
#define NWORDS 35000
#define UNITS 512
#define KC    64               // K chunk (64 fp16 = 128 B row)
#define NCH   8                // H chunks (K = 512)
#define BM    128
#define BN    64
#define NCTA  128
#define GRPSZ 8

// ---------------- static device scratch ----------------
__device__ __half g_H[2][BATCH * UNITS];          // hidden state, fp16 single plane
__device__ __half g_Whh_h[UNITS * UNITS];         // W_hh hi plane, [n][k]
__device__ __half g_Whh_l[UNITS * UNITS];         // W_hh lo plane, [n][k]
__device__ __half g_WX_h[UNITS * 128];            // W_xh hi plane, [n][k pad 128]
__device__ __half g_WX_l[UNITS * 128];
__device__ float  g_EP[(size_t)NWORDS * UNITS];   // emb @ W_xh + b_h  (fp32)
__device__ unsigned g_flag[NCTA * 32];            // per (grp,col) flags, 128B stride

// ---------------- PTX helpers ----------------
__device__ __forceinline__ uint32_t smem_to_u32(const void* p) {
    uint32_t a;
    asm("{ .reg .u64 t; cvta.to.shared.u64 t, %1; cvt.u32.u64 %0, t; }" : "=r"(a) : "l"(p));
    return a;
}
#define CP16(dst, src) \
    asm volatile("cp.async.cg.shared.global [%0], [%1], 16;" :: "r"(dst), "l"(src))
#define CP_COMMIT() asm volatile("cp.async.commit_group;" ::: "memory")
#define CP_WAIT(n)  asm volatile("cp.async.wait_group %0;" :: "n"(n) : "memory")

#define LDSM_X4(r0, r1, r2, r3, addr) \
    asm volatile("ldmatrix.sync.aligned.m8n8.x4.shared.b16 {%0,%1,%2,%3}, [%4];" \
                 : "=r"(r0), "=r"(r1), "=r"(r2), "=r"(r3) : "r"(addr))

#define MMAF16(d, a0, a1, a2, a3, b0, b1) \
    asm volatile("mma.sync.aligned.m16n8k16.row.col.f32.f16.f16.f32 " \
                 "{%0,%1,%2,%3}, {%4,%5,%6,%7}, {%8,%9}, {%0,%1,%2,%3};" \
                 : "+f"((d)[0]), "+f"((d)[1]), "+f"((d)[2]), "+f"((d)[3]) \
                 : "r"(a0), "r"(a1), "r"(a2), "r"(a3), "r"(b0), "r"(b1))

#define SWZ(bo) ((bo) ^ (((bo) >> 3) & 0x70))

// ---------------- SMEM layouts ----------------
// main: B resident 8 chunks x 2 planes x 8KB = 128KB; A 3 bufs x 16KB = 48KB
#define B_RES(p, c)  ((p) * 65536 + (c) * 8192)
#define A_OFF(buf)   (131072 + (buf) * 16384)
#define SMEM_MAIN    (131072 + 3 * 16384)          // 180224
// proj: A fp16 2 chunks x 16KB = 32KB; B 2 planes x 2 chunks x 8KB = 32KB
#define PA(ch)       ((ch) * 16384)
#define PB(p, ch)    (32768 + ((p) * 2 + (ch)) * 8192)
#define SMEM_PROJ    65536

// ---------------- prep kernels ----------------
__global__ void build_whh_kernel(const float* __restrict__ Whh) {
    int i = blockIdx.x * blockDim.x + threadIdx.x;
    if (i >= UNITS * UNITS) return;
    int n = i / UNITS;
    int k = i - n * UNITS;
    float v = Whh[(size_t)k * UNITS + n];
    __half hi = __float2half(v);
    g_Whh_h[i] = hi;
    g_Whh_l[i] = __float2half(v - __half2float(hi));
}

__global__ void build_wx_kernel(const float* __restrict__ Wxh) {
    int i = blockIdx.x * blockDim.x + threadIdx.x;
    if (i >= UNITS * 128) return;
    int n = i >> 7;
    int k = i & 127;
    float v = (k < EDIM) ? Wxh[(size_t)k * UNITS + n] : 0.0f;
    __half hi = __float2half(v);
    g_WX_h[i] = hi;
    g_WX_l[i] = __float2half(v - __half2float(hi));
}

__global__ void init_h_kernel() {
    int i = blockIdx.x * blockDim.x + threadIdx.x;
    if (i < NCTA * 32) g_flag[i] = 0u;
    if (i >= BATCH * UNITS) return;
    g_H[0][i] = __float2half(0.0f);
}

// ---------------- table projection: g_EP = emb @ W_xh + b_h ----------------
// grid (8, 274), 256 threads. A = emb rows (fp16), B = W_xh (fp16 hi/lo).
__global__ __launch_bounds__(256, 2)
void proj_gemm(const float* __restrict__ emb, const float* __restrict__ bh) {
    extern __shared__ char smem[];
    const uint32_t su = smem_to_u32(smem);
    const int tid = threadIdx.x, wid = tid >> 5, lane = tid & 31;
    const int col0 = blockIdx.x * BN;
    const int r0   = blockIdx.y * BM;

    // B planes via cp.async
    {
#pragma unroll
        for (int i = 0; i < 8; i++) {
            int u = tid + i * 256;            // 0..2047 over (plane,chunk,row,seg)
            int p  = u >> 10;
            int rem = u & 1023;
            int ch = rem >> 9;
            int r  = (rem >> 3) & 63;
            int s  = rem & 7;
            uint32_t so = SWZ((uint32_t)(r * 128 + s * 16));
            const __half* wsrc = (p == 0 ? g_WX_h : g_WX_l) + (size_t)(col0 + r) * 128 + ch * 64;
            CP16(su + PB(p, ch) + so, (const char*)wsrc + s * 16);
        }
    }
    CP_COMMIT();

    // A staging: 128 rows x 128 k (zero pad k>=100, rows >= NWORDS)
    {
#pragma unroll
        for (int i = 0; i < 64; i++) {
            int idx = tid + i * 256;
            int r = idx >> 7, k = idx & 127;
            float v = 0.0f;
            if (r0 + r < NWORDS && k < EDIM)
                v = emb[(size_t)(r0 + r) * EDIM + k];
            int ch = k >> 6, kk = k & 63;
            uint32_t so = SWZ((uint32_t)(r * 128 + kk * 2));
            *reinterpret_cast<__half*>(smem + PA(ch) + so) = __float2half(v);
        }
    }
    CP_WAIT(0);
    __syncthreads();

    const int m_base = (wid & 3) * 32;
    const int n_base = (wid >> 2) * 32;
    const int a_row = lane & 15, a_kh = (lane >> 4) * 16;
    const int b_row = ((lane >> 4) << 3) + (lane & 7), b_kh = ((lane >> 3) & 1) * 16;
    const int g = lane >> 2, tig = lane & 3;

    float acc[2][4][4];
#pragma unroll
    for (int mt = 0; mt < 2; mt++)
#pragma unroll
        for (int nt = 0; nt < 4; nt++)
#pragma unroll
            for (int q = 0; q < 4; q++) acc[mt][nt][q] = 0.0f;

    // K effective = 112 (k in [100,112) zero): 7 k-steps
#pragma unroll
    for (int ks = 0; ks < 7; ks++) {
        const int ch = ks >> 2;
        const int kb = (ks & 3) * 32;
        uint32_t A[2][4], Bh[4][2], Bl[4][2];
#pragma unroll
        for (int mt = 0; mt < 2; mt++) {
            uint32_t bo = SWZ((uint32_t)((m_base + mt * 16 + a_row) * 128 + kb + a_kh));
            LDSM_X4(A[mt][0], A[mt][1], A[mt][2], A[mt][3], su + PA(ch) + bo);
        }
#pragma unroll
        for (int np = 0; np < 2; np++) {
            uint32_t bo = SWZ((uint32_t)((n_base + np * 16 + b_row) * 128 + kb + b_kh));
            LDSM_X4(Bh[np * 2][0], Bh[np * 2][1], Bh[np * 2 + 1][0], Bh[np * 2 + 1][1],
                    su + PB(0, ch) + bo);
            LDSM_X4(Bl[np * 2][0], Bl[np * 2][1], Bl[np * 2 + 1][0], Bl[np * 2 + 1][1],
                    su + PB(1, ch) + bo);
        }
#pragma unroll
        for (int mt = 0; mt < 2; mt++)
#pragma unroll
            for (int nt = 0; nt < 4; nt++) {
                MMAF16(acc[mt][nt], A[mt][0], A[mt][1], A[mt][2], A[mt][3],
                       Bh[nt][0], Bh[nt][1]);
                MMAF16(acc[mt][nt], A[mt][0], A[mt][1], A[mt][2], A[mt][3],
                       Bl[nt][0], Bl[nt][1]);
            }
    }

    // store fp32 EP (+ bias), guard rows
#pragma unroll
    for (int mt = 0; mt < 2; mt++)
#pragma unroll
        for (int nt = 0; nt < 4; nt++) {
            const int col = col0 + n_base + nt * 8 + tig * 2;
            const float b0 = __ldg(bh + col);
            const float b1 = __ldg(bh + col + 1);
#pragma unroll
            for (int half = 0; half < 2; half++) {
                const int row = r0 + m_base + mt * 16 + g + half * 8;
                if (row < NWORDS) {
                    float2 v;
                    v.x = acc[mt][nt][half * 2] + b0;
                    v.y = acc[mt][nt][half * 2 + 1] + b1;
                    *reinterpret_cast<float2*>(g_EP + (size_t)row * UNITS + col) = v;
                }
            }
        }
}

// ---------------- persistent recurrence (K = 512, fp16, 2 products) ----------------
__global__ __launch_bounds__(512, 1)
void rnn_persistent(const int* __restrict__ inputs) {
    extern __shared__ char smem[];
    const uint32_t su = smem_to_u32(smem);
    const int tid = threadIdx.x, wid = tid >> 5, lane = tid & 31;
    const int bid = blockIdx.x;
    const int cidx = bid & 7;
    const int grp  = bid >> 3;
    const int col0 = cidx * BN, row0 = grp * BM;

    // resident B: W_hh hi/lo planes, 8 chunks
    {
#pragma unroll
        for (int i = 0; i < 8; i++) {
            int u = tid + i * 512;            // 0..4095 per plane
            int rg = u >> 3, s = u & 7;
            int ch = rg >> 6, r = rg & 63;
            uint32_t so = SWZ((uint32_t)(r * 128 + s * 16));
            size_t gs = (size_t)(col0 + r) * UNITS + ch * 64;
            CP16(su + B_RES(0, ch) + so, (const char*)(g_Whh_h + gs) + s * 16);
            CP16(su + B_RES(1, ch) + so, (const char*)(g_Whh_l + gs) + s * 16);
        }
    }
    CP_COMMIT();
    CP_WAIT(0);
    __syncthreads();

    const int m_base = (wid & 3) * 32;
    const int n_base = (wid >> 2) * 16;
    const int a_row = lane & 15, a_kh = (lane >> 4) * 16;
    const int b_row = ((lane >> 4) << 3) + (lane & 7), b_kh = ((lane >> 3) & 1) * 16;
    const int g = lane >> 2, tig = lane & 3;

    for (int t = 0; t < TLEN; t++) {
        const __half* __restrict__ Hsrc = g_H[t & 1];

        // acc init = EP gather (xw + bias, fp32, no quantization)
        float acc[2][2][4];
#pragma unroll
        for (int mt = 0; mt < 2; mt++)
#pragma unroll
            for (int half = 0; half < 2; half++) {
                const int row = row0 + m_base + mt * 16 + g + half * 8;
                const int idx = __ldg(inputs + (size_t)row * TLEN + t);
                const float* ep = g_EP + (size_t)idx * UNITS;
#pragma unroll
                for (int nt = 0; nt < 2; nt++) {
                    const int col = col0 + n_base + nt * 8 + tig * 2;
                    float2 v = __ldg(reinterpret_cast<const float2*>(ep + col));
                    acc[mt][nt][half * 2]     = v.x;
                    acc[mt][nt][half * 2 + 1] = v.y;
                }
            }

        auto spin = [&](int kc) {
            const unsigned* fp = &g_flag[(grp * 8 + kc) * 32];
            unsigned v;
            do {
                asm volatile("ld.acquire.gpu.u32 %0, [%1];" : "=r"(v) : "l"(fp));
            } while ((int)v < t);
        };
        auto load_A = [&](int kc, int buf) {
            const __half* sh = Hsrc + (size_t)row0 * UNITS + kc * KC;
#pragma unroll
            for (int i = 0; i < 2; i++) {
                int u = tid + i * 512;
                int r = u >> 3, s = u & 7;
                uint32_t so = SWZ((uint32_t)(r * 128 + s * 16));
                CP16(su + A_OFF(buf) + so, (const char*)(sh + (size_t)r * UNITS) + s * 16);
            }
            CP_COMMIT();
        };

        {
            int k0 = cidx;           spin(k0); load_A(k0, 0);
            int k1 = (cidx + 1) & 7; spin(k1); load_A(k1, 1);
        }

        uint32_t Af[2][2][4], Bhf[2][2][2], Blf[2][2][2];

        for (int ci = 0; ci < NCH; ci++) {
            const int kc = (cidx + ci) & 7;
            const int buf = ci % 3;
            if (ci < NCH - 1) { CP_WAIT(1); } else { CP_WAIT(0); }
            __syncthreads();

            const uint32_t ah  = su + A_OFF(buf);
            const uint32_t bhp = su + B_RES(0, kc);
            const uint32_t blp = su + B_RES(1, kc);

#define LDSM_KS(pb, ks) do {                                                      \
                const int kb_ = (ks) * 32;                                        \
                _Pragma("unroll")                                                 \
                for (int mt = 0; mt < 2; mt++) {                                  \
                    uint32_t bo = SWZ((uint32_t)((m_base + mt * 16 + a_row) * 128 \
                                                 + kb_ + a_kh));                  \
                    LDSM_X4(Af[pb][mt][0], Af[pb][mt][1],                         \
                            Af[pb][mt][2], Af[pb][mt][3], ah + bo);               \
                }                                                                 \
                uint32_t bo2 = SWZ((uint32_t)((n_base + b_row) * 128              \
                                              + kb_ + b_kh));                     \
                LDSM_X4(Bhf[pb][0][0], Bhf[pb][0][1],                             \
                        Bhf[pb][1][0], Bhf[pb][1][1], bhp + bo2);                 \
                LDSM_X4(Blf[pb][0][0], Blf[pb][0][1],                             \
                        Blf[pb][1][0], Blf[pb][1][1], blp + bo2);                 \
            } while (0)

#define MMA_KS(pb) do {                                                           \
                _Pragma("unroll")                                                 \
                for (int mt = 0; mt < 2; mt++) {                                  \
                    _Pragma("unroll")                                             \
                    for (int nt = 0; nt < 2; nt++) {                              \
                        MMAF16(acc[mt][nt], Af[pb][mt][0], Af[pb][mt][1],         \
                               Af[pb][mt][2], Af[pb][mt][3],                      \
                               Bhf[pb][nt][0], Bhf[pb][nt][1]);                   \
                        MMAF16(acc[mt][nt], Af[pb][mt][0], Af[pb][mt][1],         \
                               Af[pb][mt][2], Af[pb][mt][3],                      \
                               Blf[pb][nt][0], Blf[pb][nt][1]);                   \
                    }                                                             \
                }                                                                 \
            } while (0)

            LDSM_KS(0, 0);
            LDSM_KS(1, 1);
            MMA_KS(0);
            LDSM_KS(0, 2);
            MMA_KS(1);
            LDSM_KS(1, 3);
            MMA_KS(0);
            MMA_KS(1);

            if (ci + 2 < NCH) {
                int kn = (cidx + ci + 2) & 7;
                spin(kn);
                load_A(kn, (ci + 2) % 3);
            }
        }

        // ---- epilogue: tanh, fp16 store ----
        __half* __restrict__ Hdst = g_H[(t + 1) & 1];
#pragma unroll
        for (int mt = 0; mt < 2; mt++) {
#pragma unroll
            for (int nt = 0; nt < 2; nt++) {
                const int col = col0 + n_base + nt * 8 + tig * 2;
#pragma unroll
                for (int half = 0; half < 2; half++) {
                    const int row = row0 + m_base + mt * 16 + g + half * 8;
                    __half2 hp;
                    hp.x = __float2half(tanhf(acc[mt][nt][half * 2 + 0]));
                    hp.y = __float2half(tanhf(acc[mt][nt][half * 2 + 1]));
                    *reinterpret_cast<__half2*>(Hdst + (size_t)row * UNITS + col) = hp;
                }
            }
        }

        // ---- release flag ----
        __threadfence();
        __syncthreads();
        if (tid == 0) {
            unsigned* fp = &g_flag[(grp * 8 + cidx) * 32];
            asm volatile("st.release.gpu.u32 [%0], %1;"
                         :: "l"(fp), "r"((unsigned)(t + 1)) : "memory");
        }
    }
}

// ---------------- final logits ----------------
__global__ __launch_bounds__(256)
void final_logits_kernel(const float* __restrict__ Wout,
                         const float* __restrict__ bout,
                         float* __restrict__ out) {
    const __half* __restrict__ h = g_H[0];   // TLEN = 80 even -> plane 0
    int warp = threadIdx.x >> 5;
    int lane = threadIdx.x & 31;
    int row = blockIdx.x * 8 + warp;
    if (row >= BATCH) return;
    float s = 0.0f;
#pragma unroll
    for (int j = 0; j < UNITS / 32; j++) {
        int k = lane + j * 32;
        s += __half2float(h[(size_t)row * UNITS + k]) * Wout[k];
    }
#pragma unroll
    for (int o = 16; o; o >>= 1) s += __shfl_xor_sync(0xffffffff, s, o);
    if (lane == 0) out[row] = 1.0f / (1.0f + expf(-(s + bout[0])));
}

// ---------------- launch ----------------
extern "C" void kernel_launch(void* const* d_in, const int* in_sizes, int n_in,
                              void* d_out, int out_size) {
    const int*   inputs = (const int*)  d_in[0];
    const float* emb    = (const float*)d_in[1];
    const float* Wxh    = (const float*)d_in[2];
    const float* Whh    = (const float*)d_in[3];
    const float* bh     = (const float*)d_in[4];
    const float* Wout   = (const float*)d_in[5];
    const float* bout   = (const float*)d_in[6];
    float* out = (float*)d_out;

    cudaFuncSetAttribute(rnn_persistent,
                         cudaFuncAttributeMaxDynamicSharedMemorySize, SMEM_MAIN);
    cudaFuncSetAttribute(proj_gemm,
                         cudaFuncAttributeMaxDynamicSharedMemorySize, SMEM_PROJ);

    build_whh_kernel<<<(UNITS * UNITS + 255) / 256, 256>>>(Whh);
    build_wx_kernel<<<(UNITS * 128 + 255) / 256, 256>>>(Wxh);
    init_h_kernel<<<(BATCH * UNITS + 255) / 256, 256>>>();

    dim3 gp(UNITS / BN, (NWORDS + BM - 1) / BM);   // (8, 274)
    proj_gemm<<<gp, 256, SMEM_PROJ>>>(emb, bh);

    rnn_persistent<<<NCTA, 512, SMEM_MAIN>>>(inputs);

    final_logits_kernel<<<BATCH / 8, 256>>>(Wout, bout, out);
}

// round 8
// speedup vs baseline: 1.7118x; 1.1194x over previous
#include <cuda_runtime.h>
#include <cuda_fp16.h>
#include <cstdint>
#include <math.h>

// ---------------- problem dims ----------------
#define BATCH 2048
#define TLEN  80
#define EDIM  100
#define NWORDS 35000
#define UNITS 512
#define KC    64               // K chunk (64 fp16 = 128 B row)
#define NCH   8                // H chunks (K = 512)
#define BM    128
#define BN    64
#define NCTA  128
#define GRPSZ 8

// ---------------- static device scratch ----------------
__device__ __half g_H[2][BATCH * UNITS];          // hidden state, fp16 single plane
__device__ __half g_Whh_h[UNITS * UNITS];         // W_hh hi plane, [n][k]
__device__ __half g_Whh_l[UNITS * UNITS];         // W_hh lo plane, [n][k]
__device__ __half g_WX_h[UNITS * 128];            // W_xh hi plane, [n][k pad 128]
__device__ __half g_WX_l[UNITS * 128];
__device__ float  g_EP[(size_t)NWORDS * UNITS];   // emb @ W_xh + b_h  (fp32)
__device__ unsigned g_flag[NCTA * 32];            // per (grp,col) flags, 128B stride

// ---------------- PTX helpers ----------------
__device__ __forceinline__ uint32_t smem_to_u32(const void* p) {
    uint32_t a;
    asm("{ .reg .u64 t; cvta.to.shared.u64 t, %1; cvt.u32.u64 %0, t; }" : "=r"(a) : "l"(p));
    return a;
}
__device__ __forceinline__ float tanh_fast(float x) {
    float r;
    asm("tanh.approx.f32 %0, %1;" : "=f"(r) : "f"(x));
    return r;
}
#define CP16(dst, src) \
    asm volatile("cp.async.cg.shared.global [%0], [%1], 16;" :: "r"(dst), "l"(src))
#define CP_COMMIT() asm volatile("cp.async.commit_group;" ::: "memory")
#define CP_WAIT(n)  asm volatile("cp.async.wait_group %0;" :: "n"(n) : "memory")

#define LDSM_X4(r0, r1, r2, r3, addr) \
    asm volatile("ldmatrix.sync.aligned.m8n8.x4.shared.b16 {%0,%1,%2,%3}, [%4];" \
                 : "=r"(r0), "=r"(r1), "=r"(r2), "=r"(r3) : "r"(addr))

#define MMAF16(d, a0, a1, a2, a3, b0, b1) \
    asm volatile("mma.sync.aligned.m16n8k16.row.col.f32.f16.f16.f32 " \
                 "{%0,%1,%2,%3}, {%4,%5,%6,%7}, {%8,%9}, {%0,%1,%2,%3};" \
                 : "+f"((d)[0]), "+f"((d)[1]), "+f"((d)[2]), "+f"((d)[3]) \
                 : "r"(a0), "r"(a1), "r"(a2), "r"(a3), "r"(b0), "r"(b1))

#define SWZ(bo) ((bo) ^ (((bo) >> 3) & 0x70))

// ---------------- SMEM layouts ----------------
// main: B resident 8 chunks x 2 planes x 8KB = 128KB; A 4 bufs x 16KB = 64KB
#define B_RES(p, c)  ((p) * 65536 + (c) * 8192)
#define A_OFF(buf)   (131072 + (buf) * 16384)
#define SMEM_MAIN    (131072 + 4 * 16384)          // 196608
// proj: A fp16 2 chunks x 16KB = 32KB; B 2 planes x 2 chunks x 8KB = 32KB
#define PA(ch)       ((ch) * 16384)
#define PB(p, ch)    (32768 + ((p) * 2 + (ch)) * 8192)
#define SMEM_PROJ    65536

// ---------------- prep kernels ----------------
__global__ void build_whh_kernel(const float* __restrict__ Whh) {
    int i = blockIdx.x * blockDim.x + threadIdx.x;
    if (i >= UNITS * UNITS) return;
    int n = i / UNITS;
    int k = i - n * UNITS;
    float v = Whh[(size_t)k * UNITS + n];
    __half hi = __float2half(v);
    g_Whh_h[i] = hi;
    g_Whh_l[i] = __float2half(v - __half2float(hi));
}

__global__ void build_wx_kernel(const float* __restrict__ Wxh) {
    int i = blockIdx.x * blockDim.x + threadIdx.x;
    if (i >= UNITS * 128) return;
    int n = i >> 7;
    int k = i & 127;
    float v = (k < EDIM) ? Wxh[(size_t)k * UNITS + n] : 0.0f;
    __half hi = __float2half(v);
    g_WX_h[i] = hi;
    g_WX_l[i] = __float2half(v - __half2float(hi));
}

__global__ void init_h_kernel() {
    int i = blockIdx.x * blockDim.x + threadIdx.x;
    if (i < NCTA * 32) g_flag[i] = 0u;
    if (i >= BATCH * UNITS) return;
    g_H[0][i] = __float2half(0.0f);
}

// ---------------- table projection: g_EP = emb @ W_xh + b_h ----------------
__global__ __launch_bounds__(256, 2)
void proj_gemm(const float* __restrict__ emb, const float* __restrict__ bh) {
    extern __shared__ char smem[];
    const uint32_t su = smem_to_u32(smem);
    const int tid = threadIdx.x, wid = tid >> 5, lane = tid & 31;
    const int col0 = blockIdx.x * BN;
    const int r0   = blockIdx.y * BM;

    {
#pragma unroll
        for (int i = 0; i < 8; i++) {
            int u = tid + i * 256;
            int p  = u >> 10;
            int rem = u & 1023;
            int ch = rem >> 9;
            int r  = (rem >> 3) & 63;
            int s  = rem & 7;
            uint32_t so = SWZ((uint32_t)(r * 128 + s * 16));
            const __half* wsrc = (p == 0 ? g_WX_h : g_WX_l) + (size_t)(col0 + r) * 128 + ch * 64;
            CP16(su + PB(p, ch) + so, (const char*)wsrc + s * 16);
        }
    }
    CP_COMMIT();

    {
#pragma unroll
        for (int i = 0; i < 64; i++) {
            int idx = tid + i * 256;
            int r = idx >> 7, k = idx & 127;
            float v = 0.0f;
            if (r0 + r < NWORDS && k < EDIM)
                v = emb[(size_t)(r0 + r) * EDIM + k];
            int ch = k >> 6, kk = k & 63;
            uint32_t so = SWZ((uint32_t)(r * 128 + kk * 2));
            *reinterpret_cast<__half*>(smem + PA(ch) + so) = __float2half(v);
        }
    }
    CP_WAIT(0);
    __syncthreads();

    const int m_base = (wid & 3) * 32;
    const int n_base = (wid >> 2) * 32;
    const int a_row = lane & 15, a_kh = (lane >> 4) * 16;
    const int b_row = ((lane >> 4) << 3) + (lane & 7), b_kh = ((lane >> 3) & 1) * 16;
    const int g = lane >> 2, tig = lane & 3;

    float acc[2][4][4];
#pragma unroll
    for (int mt = 0; mt < 2; mt++)
#pragma unroll
        for (int nt = 0; nt < 4; nt++)
#pragma unroll
            for (int q = 0; q < 4; q++) acc[mt][nt][q] = 0.0f;

#pragma unroll
    for (int ks = 0; ks < 7; ks++) {
        const int ch = ks >> 2;
        const int kb = (ks & 3) * 32;
        uint32_t A[2][4], Bh[4][2], Bl[4][2];
#pragma unroll
        for (int mt = 0; mt < 2; mt++) {
            uint32_t bo = SWZ((uint32_t)((m_base + mt * 16 + a_row) * 128 + kb + a_kh));
            LDSM_X4(A[mt][0], A[mt][1], A[mt][2], A[mt][3], su + PA(ch) + bo);
        }
#pragma unroll
        for (int np = 0; np < 2; np++) {
            uint32_t bo = SWZ((uint32_t)((n_base + np * 16 + b_row) * 128 + kb + b_kh));
            LDSM_X4(Bh[np * 2][0], Bh[np * 2][1], Bh[np * 2 + 1][0], Bh[np * 2 + 1][1],
                    su + PB(0, ch) + bo);
            LDSM_X4(Bl[np * 2][0], Bl[np * 2][1], Bl[np * 2 + 1][0], Bl[np * 2 + 1][1],
                    su + PB(1, ch) + bo);
        }
#pragma unroll
        for (int mt = 0; mt < 2; mt++)
#pragma unroll
            for (int nt = 0; nt < 4; nt++) {
                MMAF16(acc[mt][nt], A[mt][0], A[mt][1], A[mt][2], A[mt][3],
                       Bh[nt][0], Bh[nt][1]);
                MMAF16(acc[mt][nt], A[mt][0], A[mt][1], A[mt][2], A[mt][3],
                       Bl[nt][0], Bl[nt][1]);
            }
    }

#pragma unroll
    for (int mt = 0; mt < 2; mt++)
#pragma unroll
        for (int nt = 0; nt < 4; nt++) {
            const int col = col0 + n_base + nt * 8 + tig * 2;
            const float b0 = __ldg(bh + col);
            const float b1 = __ldg(bh + col + 1);
#pragma unroll
            for (int half = 0; half < 2; half++) {
                const int row = r0 + m_base + mt * 16 + g + half * 8;
                if (row < NWORDS) {
                    float2 v;
                    v.x = acc[mt][nt][half * 2] + b0;
                    v.y = acc[mt][nt][half * 2 + 1] + b1;
                    *reinterpret_cast<float2*>(g_EP + (size_t)row * UNITS + col) = v;
                }
            }
        }
}

// ---------------- persistent recurrence (K = 512, fp16, 2 products) ----------------
__global__ __launch_bounds__(512, 1)
void rnn_persistent(const int* __restrict__ inputs) {
    extern __shared__ char smem[];
    const uint32_t su = smem_to_u32(smem);
    const int tid = threadIdx.x, wid = tid >> 5, lane = tid & 31;
    const int bid = blockIdx.x;
    const int cidx = bid & 7;
    const int grp  = bid >> 3;
    const int col0 = cidx * BN, row0 = grp * BM;

    // resident B: W_hh hi/lo planes, 8 chunks
    {
#pragma unroll
        for (int i = 0; i < 8; i++) {
            int u = tid + i * 512;
            int rg = u >> 3, s = u & 7;
            int ch = rg >> 6, r = rg & 63;
            uint32_t so = SWZ((uint32_t)(r * 128 + s * 16));
            size_t gs = (size_t)(col0 + r) * UNITS + ch * 64;
            CP16(su + B_RES(0, ch) + so, (const char*)(g_Whh_h + gs) + s * 16);
            CP16(su + B_RES(1, ch) + so, (const char*)(g_Whh_l + gs) + s * 16);
        }
    }
    CP_COMMIT();
    // prefill A buffer 0 with zeros (H_0 own chunk)
    {
        uint4 z = make_uint4(0, 0, 0, 0);
        reinterpret_cast<uint4*>(smem + A_OFF(0))[tid]       = z;
        reinterpret_cast<uint4*>(smem + A_OFF(0))[tid + 512] = z;
    }
    CP_WAIT(0);
    __syncthreads();

    const int m_base = (wid & 3) * 32;
    const int n_base = (wid >> 2) * 16;
    const int a_row = lane & 15, a_kh = (lane >> 4) * 16;
    const int b_row = ((lane >> 4) << 3) + (lane & 7), b_kh = ((lane >> 3) & 1) * 16;
    const int g = lane >> 2, tig = lane & 3;

    for (int t = 0; t < TLEN; t++) {
        const __half* __restrict__ Hsrc = g_H[t & 1];

        // acc init = EP gather (fp32, bias folded) — issue LDGs early
        float acc[2][2][4];
#pragma unroll
        for (int mt = 0; mt < 2; mt++)
#pragma unroll
            for (int half = 0; half < 2; half++) {
                const int row = row0 + m_base + mt * 16 + g + half * 8;
                const int idx = __ldg(inputs + (size_t)row * TLEN + t);
                const float* ep = g_EP + (size_t)idx * UNITS;
#pragma unroll
                for (int nt = 0; nt < 2; nt++) {
                    const int col = col0 + n_base + nt * 8 + tig * 2;
                    float2 v = __ldg(reinterpret_cast<const float2*>(ep + col));
                    acc[mt][nt][half * 2]     = v.x;
                    acc[mt][nt][half * 2 + 1] = v.y;
                }
            }

        auto spin = [&](int kc) {
            const unsigned* fp = &g_flag[(grp * 8 + kc) * 32];
            unsigned v;
            do {
                asm volatile("ld.acquire.gpu.u32 %0, [%1];" : "=r"(v) : "l"(fp));
            } while ((int)v < t);
        };
        auto load_A = [&](int kc, int buf) {
            const __half* sh = Hsrc + (size_t)row0 * UNITS + kc * KC;
#pragma unroll
            for (int i = 0; i < 2; i++) {
                int u = tid + i * 512;
                int r = u >> 3, s = u & 7;
                uint32_t so = SWZ((uint32_t)(r * 128 + s * 16));
                CP16(su + A_OFF(buf) + so, (const char*)(sh + (size_t)r * UNITS) + s * 16);
            }
            CP_COMMIT();
        };

        uint32_t Af[2][2][4], Bhf[2][2][2], Blf[2][2][2];

#define LDSM_KS(pb, ks, ah, bhp, blp) do {                                        \
            const int kb_ = (ks) * 32;                                            \
            _Pragma("unroll")                                                     \
            for (int mt = 0; mt < 2; mt++) {                                      \
                uint32_t bo = SWZ((uint32_t)((m_base + mt * 16 + a_row) * 128     \
                                             + kb_ + a_kh));                      \
                LDSM_X4(Af[pb][mt][0], Af[pb][mt][1],                             \
                        Af[pb][mt][2], Af[pb][mt][3], (ah) + bo);                 \
            }                                                                     \
            uint32_t bo2 = SWZ((uint32_t)((n_base + b_row) * 128 + kb_ + b_kh));  \
            LDSM_X4(Bhf[pb][0][0], Bhf[pb][0][1],                                 \
                    Bhf[pb][1][0], Bhf[pb][1][1], (bhp) + bo2);                   \
            LDSM_X4(Blf[pb][0][0], Blf[pb][0][1],                                 \
                    Blf[pb][1][0], Blf[pb][1][1], (blp) + bo2);                   \
        } while (0)

#define MMA_KS(pb) do {                                                           \
            _Pragma("unroll")                                                     \
            for (int mt = 0; mt < 2; mt++) {                                      \
                _Pragma("unroll")                                                 \
                for (int nt = 0; nt < 2; nt++) {                                  \
                    MMAF16(acc[mt][nt], Af[pb][mt][0], Af[pb][mt][1],             \
                           Af[pb][mt][2], Af[pb][mt][3],                          \
                           Bhf[pb][nt][0], Bhf[pb][nt][1]);                       \
                    MMAF16(acc[mt][nt], Af[pb][mt][0], Af[pb][mt][1],             \
                           Af[pb][mt][2], Af[pb][mt][3],                          \
                           Blf[pb][nt][0], Blf[pb][nt][1]);                       \
                }                                                                 \
            }                                                                     \
        } while (0)

#define PROC_CHUNK(ah, bhp, blp) do {                                             \
            LDSM_KS(0, 0, ah, bhp, blp);                                          \
            LDSM_KS(1, 1, ah, bhp, blp);                                          \
            MMA_KS(0);                                                            \
            LDSM_KS(0, 2, ah, bhp, blp);                                          \
            MMA_KS(1);                                                            \
            LDSM_KS(1, 3, ah, bhp, blp);                                          \
            MMA_KS(0);                                                            \
            MMA_KS(1);                                                            \
        } while (0)

        // --- G1: chunk cidx+1 ---
        {
            int k1 = (cidx + 1) & 7;
            spin(k1);
            load_A(k1, 1);
        }
        // --- ci = 0: own chunk, already in smem buf 0 (epilogue-forwarded) ---
        PROC_CHUNK(su + A_OFF(0), su + B_RES(0, cidx), su + B_RES(1, cidx));
        // --- G2, G3 ---
        {
            int k2 = (cidx + 2) & 7; spin(k2); load_A(k2, 2);
            int k3 = (cidx + 3) & 7; spin(k3); load_A(k3, 3);
        }

        for (int ci = 1; ci < NCH; ci++) {
            if (ci < 6)      { CP_WAIT(2); }
            else if (ci == 6){ CP_WAIT(1); }
            else             { CP_WAIT(0); }
            __syncthreads();
            if (ci <= 4) {
                int kn = (cidx + ci + 3) & 7;
                spin(kn);
                load_A(kn, (ci + 3) & 3);
            }
            const int kc = (cidx + ci) & 7;
            const uint32_t ah = su + A_OFF(ci & 3);
            PROC_CHUNK(ah, su + B_RES(0, kc), su + B_RES(1, kc));
        }

        // ---- epilogue: tanh.approx, fp16 store to global + own-chunk smem fwd ----
        __half* __restrict__ Hdst = g_H[(t + 1) & 1];
#pragma unroll
        for (int mt = 0; mt < 2; mt++) {
#pragma unroll
            for (int nt = 0; nt < 2; nt++) {
                const int ncol = n_base + nt * 8 + tig * 2;   // 0..63 local k
                const int col  = col0 + ncol;
#pragma unroll
                for (int half = 0; half < 2; half++) {
                    const int lrow = m_base + mt * 16 + g + half * 8;  // 0..127
                    const int row  = row0 + lrow;
                    __half2 hp;
                    hp.x = __float2half(tanh_fast(acc[mt][nt][half * 2 + 0]));
                    hp.y = __float2half(tanh_fast(acc[mt][nt][half * 2 + 1]));
                    *reinterpret_cast<__half2*>(Hdst + (size_t)row * UNITS + col) = hp;
                    uint32_t so = SWZ((uint32_t)(lrow * 128 + ncol * 2));
                    *reinterpret_cast<__half2*>(smem + A_OFF(0) + so) = hp;
                }
            }
        }

        // ---- release: CTA-wide hb to tid0, then gpu-scope release store ----
        __syncthreads();
        if (tid == 0) {
            __threadfence();
            unsigned* fp = &g_flag[(grp * 8 + cidx) * 32];
            asm volatile("st.release.gpu.u32 [%0], %1;"
                         :: "l"(fp), "r"((unsigned)(t + 1)) : "memory");
        }
    }
}

// ---------------- final logits ----------------
__global__ __launch_bounds__(256)
void final_logits_kernel(const float* __restrict__ Wout,
                         const float* __restrict__ bout,
                         float* __restrict__ out) {
    const __half* __restrict__ h = g_H[0];   // TLEN = 80 even -> plane 0
    int warp = threadIdx.x >> 5;
    int lane = threadIdx.x & 31;
    int row = blockIdx.x * 8 + warp;
    if (row >= BATCH) return;
    float s = 0.0f;
#pragma unroll
    for (int j = 0; j < UNITS / 32; j++) {
        int k = lane + j * 32;
        s += __half2float(h[(size_t)row * UNITS + k]) * Wout[k];
    }
#pragma unroll
    for (int o = 16; o; o >>= 1) s += __shfl_xor_sync(0xffffffff, s, o);
    if (lane == 0) out[row] = 1.0f / (1.0f + expf(-(s + bout[0])));
}

// ---------------- launch ----------------
extern "C" void kernel_launch(void* const* d_in, const int* in_sizes, int n_in,
                              void* d_out, int out_size) {
    const int*   inputs = (const int*)  d_in[0];
    const float* emb    = (const float*)d_in[1];
    const float* Wxh    = (const float*)d_in[2];
    const float* Whh    = (const float*)d_in[3];
    const float* bh     = (const float*)d_in[4];
    const float* Wout   = (const float*)d_in[5];
    const float* bout   = (const float*)d_in[6];
    float* out = (float*)d_out;

    cudaFuncSetAttribute(rnn_persistent,
                         cudaFuncAttributeMaxDynamicSharedMemorySize, SMEM_MAIN);
    cudaFuncSetAttribute(proj_gemm,
                         cudaFuncAttributeMaxDynamicSharedMemorySize, SMEM_PROJ);

    build_whh_kernel<<<(UNITS * UNITS + 255) / 256, 256>>>(Whh);
    build_wx_kernel<<<(UNITS * 128 + 255) / 256, 256>>>(Wxh);
    init_h_kernel<<<(BATCH * UNITS + 255) / 256, 256>>>();

    dim3 gp(UNITS / BN, (NWORDS + BM - 1) / BM);   // (8, 274)
    proj_gemm<<<gp, 256, SMEM_PROJ>>>(emb, bh);

    rnn_persistent<<<NCTA, 512, SMEM_MAIN>>>(inputs);

    final_logits_kernel<<<BATCH / 8, 256>>>(Wout, bout, out);
}

// round 9
// speedup vs baseline: 1.9614x; 1.1458x over previous
#include <cuda_runtime.h>
#include <cuda_fp16.h>
#include <cstdint>
#include <math.h>

// ---------------- problem dims ----------------
#define BATCH 2048
#define TLEN  80
#define EDIM  100
#define NWORDS 35000
#define UNITS 512
#define KC    64               // K chunk (64 fp16 = 128 B row)
#define BM    128
#define BN    64
#define NCTA  128
#define GRPSZ 8

// ---------------- static device scratch ----------------
__device__ __half g_H[2][BATCH * UNITS];          // hidden state, fp16
__device__ __half g_Whh_h[UNITS * UNITS];         // W_hh hi plane, [n][k]
__device__ __half g_Whh_l[UNITS * UNITS];         // W_hh lo plane, [n][k]
__device__ __half g_WX_h[UNITS * 128];            // W_xh hi plane, [n][k pad 128]
__device__ __half g_WX_l[UNITS * 128];
__device__ float  g_EP[(size_t)NWORDS * UNITS];   // emb @ W_xh + b_h  (fp32)
__device__ unsigned g_flag[NCTA * 32];            // per (grp,col) flags, 128B stride

// ---------------- PTX helpers ----------------
__device__ __forceinline__ uint32_t smem_to_u32(const void* p) {
    uint32_t a;
    asm("{ .reg .u64 t; cvta.to.shared.u64 t, %1; cvt.u32.u64 %0, t; }" : "=r"(a) : "l"(p));
    return a;
}
__device__ __forceinline__ float tanh_fast(float x) {
    float r;
    asm("tanh.approx.f32 %0, %1;" : "=f"(r) : "f"(x));
    return r;
}
#define CP16(dst, src) \
    asm volatile("cp.async.cg.shared.global [%0], [%1], 16;" :: "r"(dst), "l"(src))
#define CP_COMMIT() asm volatile("cp.async.commit_group;" ::: "memory")
#define CP_WAIT(n)  asm volatile("cp.async.wait_group %0;" :: "n"(n) : "memory")

#define LDSM_X4(r0, r1, r2, r3, addr) \
    asm volatile("ldmatrix.sync.aligned.m8n8.x4.shared.b16 {%0,%1,%2,%3}, [%4];" \
                 : "=r"(r0), "=r"(r1), "=r"(r2), "=r"(r3) : "r"(addr))

#define MMAF16(d, a0, a1, a2, a3, b0, b1) \
    asm volatile("mma.sync.aligned.m16n8k16.row.col.f32.f16.f16.f32 " \
                 "{%0,%1,%2,%3}, {%4,%5,%6,%7}, {%8,%9}, {%0,%1,%2,%3};" \
                 : "+f"((d)[0]), "+f"((d)[1]), "+f"((d)[2]), "+f"((d)[3]) \
                 : "r"(a0), "r"(a1), "r"(a2), "r"(a3), "r"(b0), "r"(b1))

#define SWZ(bo) ((bo) ^ (((bo) >> 3) & 0x70))

// non-aligned barriers (legal from group-divergent but warp-uniform points)
#define BAR_CTA()  asm volatile("barrier.sync 0;" ::: "memory")
#define BAR_G(id)  asm volatile("barrier.sync %0, 256;" :: "n"(id) : "memory")

// ---------------- SMEM layouts ----------------
// main: B resident 8 chunks x 2 planes x 8KB = 128KB; A 6 bufs x 16KB = 96KB
// stage (g1 partial acc, 128 x 72 fp32 = 36KB) overlays A bufs 3..5.
#define B_RES(p, c)  ((p) * 65536 + (c) * 8192)
#define A_OFF(buf)   (131072 + (buf) * 16384)
#define STAGE_OFF    A_OFF(3)
#define STG_STRIDE   72
#define SMEM_MAIN    (131072 + 6 * 16384)          // 229376
// proj: A fp16 2 chunks x 16KB = 32KB; B 2 planes x 2 chunks x 8KB = 32KB
#define PA(ch)       ((ch) * 16384)
#define PB(p, ch)    (32768 + ((p) * 2 + (ch)) * 8192)
#define SMEM_PROJ    65536

// ---------------- prep kernels ----------------
__global__ void build_whh_kernel(const float* __restrict__ Whh) {
    int i = blockIdx.x * blockDim.x + threadIdx.x;
    if (i >= UNITS * UNITS) return;
    int n = i / UNITS;
    int k = i - n * UNITS;
    float v = Whh[(size_t)k * UNITS + n];
    __half hi = __float2half(v);
    g_Whh_h[i] = hi;
    g_Whh_l[i] = __float2half(v - __half2float(hi));
}

__global__ void build_wx_kernel(const float* __restrict__ Wxh) {
    int i = blockIdx.x * blockDim.x + threadIdx.x;
    if (i >= UNITS * 128) return;
    int n = i >> 7;
    int k = i & 127;
    float v = (k < EDIM) ? Wxh[(size_t)k * UNITS + n] : 0.0f;
    __half hi = __float2half(v);
    g_WX_h[i] = hi;
    g_WX_l[i] = __float2half(v - __half2float(hi));
}

__global__ void init_h_kernel() {
    int i = blockIdx.x * blockDim.x + threadIdx.x;
    if (i < NCTA * 32) g_flag[i] = 0u;
    if (i >= BATCH * UNITS) return;
    g_H[0][i] = __float2half(0.0f);
}

// ---------------- table projection: g_EP = emb @ W_xh + b_h ----------------
__global__ __launch_bounds__(256, 2)
void proj_gemm(const float* __restrict__ emb, const float* __restrict__ bh) {
    extern __shared__ char smem[];
    const uint32_t su = smem_to_u32(smem);
    const int tid = threadIdx.x, wid = tid >> 5, lane = tid & 31;
    const int col0 = blockIdx.x * BN;
    const int r0   = blockIdx.y * BM;

    {
#pragma unroll
        for (int i = 0; i < 8; i++) {
            int u = tid + i * 256;
            int p  = u >> 10;
            int rem = u & 1023;
            int ch = rem >> 9;
            int r  = (rem >> 3) & 63;
            int s  = rem & 7;
            uint32_t so = SWZ((uint32_t)(r * 128 + s * 16));
            const __half* wsrc = (p == 0 ? g_WX_h : g_WX_l) + (size_t)(col0 + r) * 128 + ch * 64;
            CP16(su + PB(p, ch) + so, (const char*)wsrc + s * 16);
        }
    }
    CP_COMMIT();

    {
#pragma unroll
        for (int i = 0; i < 64; i++) {
            int idx = tid + i * 256;
            int r = idx >> 7, k = idx & 127;
            float v = 0.0f;
            if (r0 + r < NWORDS && k < EDIM)
                v = emb[(size_t)(r0 + r) * EDIM + k];
            int ch = k >> 6, kk = k & 63;
            uint32_t so = SWZ((uint32_t)(r * 128 + kk * 2));
            *reinterpret_cast<__half*>(smem + PA(ch) + so) = __float2half(v);
        }
    }
    CP_WAIT(0);
    __syncthreads();

    const int m_base = (wid & 3) * 32;
    const int n_base = (wid >> 2) * 32;
    const int a_row = lane & 15, a_kh = (lane >> 4) * 16;
    const int b_row = ((lane >> 4) << 3) + (lane & 7), b_kh = ((lane >> 3) & 1) * 16;
    const int lg = lane >> 2, tig = lane & 3;

    float acc[2][4][4];
#pragma unroll
    for (int mt = 0; mt < 2; mt++)
#pragma unroll
        for (int nt = 0; nt < 4; nt++)
#pragma unroll
            for (int q = 0; q < 4; q++) acc[mt][nt][q] = 0.0f;

#pragma unroll
    for (int ks = 0; ks < 7; ks++) {
        const int ch = ks >> 2;
        const int kb = (ks & 3) * 32;
        uint32_t A[2][4], Bh[4][2], Bl[4][2];
#pragma unroll
        for (int mt = 0; mt < 2; mt++) {
            uint32_t bo = SWZ((uint32_t)((m_base + mt * 16 + a_row) * 128 + kb + a_kh));
            LDSM_X4(A[mt][0], A[mt][1], A[mt][2], A[mt][3], su + PA(ch) + bo);
        }
#pragma unroll
        for (int np = 0; np < 2; np++) {
            uint32_t bo = SWZ((uint32_t)((n_base + np * 16 + b_row) * 128 + kb + b_kh));
            LDSM_X4(Bh[np * 2][0], Bh[np * 2][1], Bh[np * 2 + 1][0], Bh[np * 2 + 1][1],
                    su + PB(0, ch) + bo);
            LDSM_X4(Bl[np * 2][0], Bl[np * 2][1], Bl[np * 2 + 1][0], Bl[np * 2 + 1][1],
                    su + PB(1, ch) + bo);
        }
#pragma unroll
        for (int mt = 0; mt < 2; mt++)
#pragma unroll
            for (int nt = 0; nt < 4; nt++) {
                MMAF16(acc[mt][nt], A[mt][0], A[mt][1], A[mt][2], A[mt][3],
                       Bh[nt][0], Bh[nt][1]);
                MMAF16(acc[mt][nt], A[mt][0], A[mt][1], A[mt][2], A[mt][3],
                       Bl[nt][0], Bl[nt][1]);
            }
    }

#pragma unroll
    for (int mt = 0; mt < 2; mt++)
#pragma unroll
        for (int nt = 0; nt < 4; nt++) {
            const int col = col0 + n_base + nt * 8 + tig * 2;
            const float b0 = __ldg(bh + col);
            const float b1 = __ldg(bh + col + 1);
#pragma unroll
            for (int half = 0; half < 2; half++) {
                const int row = r0 + m_base + mt * 16 + lg + half * 8;
                if (row < NWORDS) {
                    float2 v;
                    v.x = acc[mt][nt][half * 2] + b0;
                    v.y = acc[mt][nt][half * 2 + 1] + b1;
                    *reinterpret_cast<float2*>(g_EP + (size_t)row * UNITS + col) = v;
                }
            }
        }
}

// ---------------- persistent recurrence: split-K(2), 32x32 warp tiles ----------------
__global__ __launch_bounds__(512, 1)
void rnn_persistent(const int* __restrict__ inputs) {
    extern __shared__ char smem[];
    const uint32_t su = smem_to_u32(smem);
    const int tid = threadIdx.x, wid = tid >> 5, lane = tid & 31;
    const int kg  = wid >> 3;                      // k-group 0/1 (warp-uniform)
    const int wg  = wid & 7;
    const int tg  = tid & 255;                     // tid within group
    const int bid = blockIdx.x;
    const int cidx = bid & 7;
    const int grp  = bid >> 3;
    const int col0 = cidx * BN, row0 = grp * BM;

    // resident B: W_hh hi/lo planes, 8 chunks (full CTA cooperative)
    {
#pragma unroll
        for (int i = 0; i < 8; i++) {
            int u = tid + i * 512;
            int rg = u >> 3, s = u & 7;
            int ch = rg >> 6, r = rg & 63;
            uint32_t so = SWZ((uint32_t)(r * 128 + s * 16));
            size_t gs = (size_t)(col0 + r) * UNITS + ch * 64;
            CP16(su + B_RES(0, ch) + so, (const char*)(g_Whh_h + gs) + s * 16);
            CP16(su + B_RES(1, ch) + so, (const char*)(g_Whh_l + gs) + s * 16);
        }
    }
    CP_COMMIT();
    // prefill A buffer 0 with zeros (H_0 own chunk, forwarded path)
    {
        uint4 z = make_uint4(0, 0, 0, 0);
        reinterpret_cast<uint4*>(smem + A_OFF(0))[tid]       = z;
        reinterpret_cast<uint4*>(smem + A_OFF(0))[tid + 512] = z;
    }
    CP_WAIT(0);
    __syncthreads();

    const int m_base = (wg & 3) * 32;
    const int n_base = (wg >> 2) * 32;
    const int a_row = lane & 15, a_kh = (lane >> 4) * 16;
    const int b_row = ((lane >> 4) << 3) + (lane & 7), b_kh = ((lane >> 3) & 1) * 16;
    const int lg = lane >> 2, tig = lane & 3;

    for (int t = 0; t < TLEN; t++) {
        const __half* __restrict__ Hsrc = g_H[t & 1];

        float acc[2][4][4];
#pragma unroll
        for (int mt = 0; mt < 2; mt++)
#pragma unroll
            for (int nt = 0; nt < 4; nt++)
#pragma unroll
                for (int q = 0; q < 4; q++) acc[mt][nt][q] = 0.0f;

        auto spin = [&](int kc) {
            const unsigned* fp = &g_flag[(grp * 8 + kc) * 32];
            unsigned v;
            do {
                asm volatile("ld.acquire.gpu.u32 %0, [%1];" : "=r"(v) : "l"(fp));
            } while ((int)v < t);
        };
        auto load_A = [&](int kc, int buf) {   // 256 threads of one group
            const __half* sh = Hsrc + (size_t)row0 * UNITS + kc * KC;
#pragma unroll
            for (int i = 0; i < 4; i++) {
                int u = tg + i * 256;
                int r = u >> 3, s = u & 7;
                uint32_t so = SWZ((uint32_t)(r * 128 + s * 16));
                CP16(su + A_OFF(buf) + so, (const char*)(sh + (size_t)r * UNITS) + s * 16);
            }
            CP_COMMIT();
        };

#define PROC_CHUNK(abuf, kc) do {                                             \
            const uint32_t ah_ = su + A_OFF(abuf);                            \
            const uint32_t bh_ = su + B_RES(0, (kc));                         \
            const uint32_t bl_ = su + B_RES(1, (kc));                         \
            _Pragma("unroll")                                                 \
            for (int ks_ = 0; ks_ < 4; ks_++) {                               \
                const int kb_ = ks_ * 32;                                     \
                uint32_t Af_[2][4], Bh_[4][2], Bl_[4][2];                     \
                _Pragma("unroll")                                             \
                for (int mt_ = 0; mt_ < 2; mt_++) {                           \
                    uint32_t bo = SWZ((uint32_t)((m_base + mt_ * 16 + a_row)  \
                                                 * 128 + kb_ + a_kh));        \
                    LDSM_X4(Af_[mt_][0], Af_[mt_][1], Af_[mt_][2],            \
                            Af_[mt_][3], ah_ + bo);                           \
                }                                                             \
                _Pragma("unroll")                                             \
                for (int np_ = 0; np_ < 2; np_++) {                           \
                    uint32_t bo = SWZ((uint32_t)((n_base + np_ * 16 + b_row)  \
                                                 * 128 + kb_ + b_kh));        \
                    LDSM_X4(Bh_[np_ * 2][0], Bh_[np_ * 2][1],                 \
                            Bh_[np_ * 2 + 1][0], Bh_[np_ * 2 + 1][1],         \
                            bh_ + bo);                                        \
                    LDSM_X4(Bl_[np_ * 2][0], Bl_[np_ * 2][1],                 \
                            Bl_[np_ * 2 + 1][0], Bl_[np_ * 2 + 1][1],         \
                            bl_ + bo);                                        \
                }                                                             \
                _Pragma("unroll")                                             \
                for (int mt_ = 0; mt_ < 2; mt_++)                             \
                    _Pragma("unroll")                                         \
                    for (int nt_ = 0; nt_ < 4; nt_++) {                       \
                        MMAF16(acc[mt_][nt_], Af_[mt_][0], Af_[mt_][1],       \
                               Af_[mt_][2], Af_[mt_][3],                      \
                               Bh_[nt_][0], Bh_[nt_][1]);                     \
                        MMAF16(acc[mt_][nt_], Af_[mt_][0], Af_[mt_][1],       \
                               Af_[mt_][2], Af_[mt_][3],                      \
                               Bl_[nt_][0], Bl_[nt_][1]);                     \
                    }                                                         \
            }                                                                 \
        } while (0)

        if (kg == 0) {
            // ---- EP gather into regs (consumed only at epilogue) ----
            float ep[2][4][4];
#pragma unroll
            for (int mt = 0; mt < 2; mt++)
#pragma unroll
                for (int half = 0; half < 2; half++) {
                    const int row = row0 + m_base + mt * 16 + lg + half * 8;
                    const int idx = __ldg(inputs + (size_t)row * TLEN + t);
                    const float* eprow = g_EP + (size_t)idx * UNITS + col0;
#pragma unroll
                    for (int nt = 0; nt < 4; nt++) {
                        float2 v = __ldg(reinterpret_cast<const float2*>(
                                             eprow + n_base + nt * 8 + tig * 2));
                        ep[mt][nt][half * 2]     = v.x;
                        ep[mt][nt][half * 2 + 1] = v.y;
                    }
                }

            const int k1 = (cidx + 1) & 7, k2 = (cidx + 2) & 7, k3 = (cidx + 3) & 7;
            spin(k1); load_A(k1, 1);
            spin(k2); load_A(k2, 2);
            PROC_CHUNK(0, cidx);               // own chunk, smem-forwarded
            CP_WAIT(1); BAR_G(1);              // k1 in; buf0 consumed group-wide
            spin(k3); load_A(k3, 0);
            PROC_CHUNK(1, k1);
            CP_WAIT(1); BAR_G(1);              // k2 in
            PROC_CHUNK(2, k2);
            CP_WAIT(0); BAR_G(1);              // k3 in
            PROC_CHUNK(0, k3);

            BAR_CTA();                          // stage ready (pairs with g1 #1)

            // ---- combine + tanh + store + forward ----
            __half* __restrict__ Hdst = g_H[(t + 1) & 1];
            const float* stg = reinterpret_cast<const float*>(smem + STAGE_OFF);
#pragma unroll
            for (int mt = 0; mt < 2; mt++)
#pragma unroll
                for (int nt = 0; nt < 4; nt++) {
                    const int col_l = n_base + nt * 8 + tig * 2;
                    const int col   = col0 + col_l;
#pragma unroll
                    for (int half = 0; half < 2; half++) {
                        const int row_l = m_base + mt * 16 + lg + half * 8;
                        float2 s2 = *reinterpret_cast<const float2*>(
                                        stg + row_l * STG_STRIDE + col_l);
                        float v0 = tanh_fast(acc[mt][nt][half * 2 + 0] + s2.x
                                             + ep[mt][nt][half * 2 + 0]);
                        float v1 = tanh_fast(acc[mt][nt][half * 2 + 1] + s2.y
                                             + ep[mt][nt][half * 2 + 1]);
                        __half2 hp;
                        hp.x = __float2half(v0);
                        hp.y = __float2half(v1);
                        *reinterpret_cast<__half2*>(
                            Hdst + (size_t)(row0 + row_l) * UNITS + col) = hp;
                        uint32_t so = SWZ((uint32_t)(row_l * 128 + col_l * 2));
                        *reinterpret_cast<__half2*>(smem + A_OFF(0) + so) = hp;
                    }
                }

            BAR_CTA();                          // pairs with g1 #2
            if (tid == 0) {
                __threadfence();
                unsigned* fp = &g_flag[(grp * 8 + cidx) * 32];
                asm volatile("st.release.gpu.u32 [%0], %1;"
                             :: "l"(fp), "r"((unsigned)(t + 1)) : "memory");
            }
        } else {
            const int k4 = (cidx + 4) & 7, k5 = (cidx + 5) & 7;
            const int k6 = (cidx + 6) & 7, k7 = (cidx + 7) & 7;
            spin(k4); load_A(k4, 3);
            spin(k5); load_A(k5, 4);
            spin(k6); load_A(k6, 5);
            CP_WAIT(2); BAR_G(2);              // k4 in
            PROC_CHUNK(3, k4);
            BAR_G(2);                          // buf3 consumed group-wide
            spin(k7); load_A(k7, 3);
            CP_WAIT(2); BAR_G(2);              // k5 in
            PROC_CHUNK(4, k5);
            CP_WAIT(1); BAR_G(2);              // k6 in
            PROC_CHUNK(5, k6);
            CP_WAIT(0); BAR_G(2);              // k7 in
            PROC_CHUNK(3, k7);
            BAR_G(2);                          // buf3 reads done before stage write

            // ---- stage partial acc (overlays bufs 3..5, all consumed) ----
            float* stg = reinterpret_cast<float*>(smem + STAGE_OFF);
#pragma unroll
            for (int mt = 0; mt < 2; mt++)
#pragma unroll
                for (int nt = 0; nt < 4; nt++) {
                    const int col_l = n_base + nt * 8 + tig * 2;
#pragma unroll
                    for (int half = 0; half < 2; half++) {
                        const int row_l = m_base + mt * 16 + lg + half * 8;
                        float2 w;
                        w.x = acc[mt][nt][half * 2 + 0];
                        w.y = acc[mt][nt][half * 2 + 1];
                        *reinterpret_cast<float2*>(
                            stg + row_l * STG_STRIDE + col_l) = w;
                    }
                }
            BAR_CTA();                          // #1: stage visible to g0
            BAR_CTA();                          // #2: g0 done with stage; bufs reusable
        }
#undef PROC_CHUNK
    }
}

// ---------------- final logits ----------------
__global__ __launch_bounds__(256)
void final_logits_kernel(const float* __restrict__ Wout,
                         const float* __restrict__ bout,
                         float* __restrict__ out) {
    const __half* __restrict__ h = g_H[0];   // TLEN = 80 even -> plane 0
    int warp = threadIdx.x >> 5;
    int lane = threadIdx.x & 31;
    int row = blockIdx.x * 8 + warp;
    if (row >= BATCH) return;
    float s = 0.0f;
#pragma unroll
    for (int j = 0; j < UNITS / 32; j++) {
        int k = lane + j * 32;
        s += __half2float(h[(size_t)row * UNITS + k]) * Wout[k];
    }
#pragma unroll
    for (int o = 16; o; o >>= 1) s += __shfl_xor_sync(0xffffffff, s, o);
    if (lane == 0) out[row] = 1.0f / (1.0f + expf(-(s + bout[0])));
}

// ---------------- launch ----------------
extern "C" void kernel_launch(void* const* d_in, const int* in_sizes, int n_in,
                              void* d_out, int out_size) {
    const int*   inputs = (const int*)  d_in[0];
    const float* emb    = (const float*)d_in[1];
    const float* Wxh    = (const float*)d_in[2];
    const float* Whh    = (const float*)d_in[3];
    const float* bh     = (const float*)d_in[4];
    const float* Wout   = (const float*)d_in[5];
    const float* bout   = (const float*)d_in[6];
    float* out = (float*)d_out;

    cudaFuncSetAttribute(rnn_persistent,
                         cudaFuncAttributeMaxDynamicSharedMemorySize, SMEM_MAIN);
    cudaFuncSetAttribute(proj_gemm,
                         cudaFuncAttributeMaxDynamicSharedMemorySize, SMEM_PROJ);

    build_whh_kernel<<<(UNITS * UNITS + 255) / 256, 256>>>(Whh);
    build_wx_kernel<<<(UNITS * 128 + 255) / 256, 256>>>(Wxh);
    init_h_kernel<<<(BATCH * UNITS + 255) / 256, 256>>>();

    dim3 gp(UNITS / BN, (NWORDS + BM - 1) / BM);   // (8, 274)
    proj_gemm<<<gp, 256, SMEM_PROJ>>>(emb, bh);

    rnn_persistent<<<NCTA, 512, SMEM_MAIN>>>(inputs);

    final_logits_kernel<<<BATCH / 8, 256>>>(Wout, bout, out);
}

// round 10
// speedup vs baseline: 2.5051x; 1.2772x over previous
#include <cuda_runtime.h>
#include <cuda_fp16.h>
#include <cstdint>
#include <math.h>

// ---------------- problem dims ----------------
#define BATCH 2048
#define TLEN  80
#define EDIM  100
#define NWORDS 35000
#define UNITS 512
#define KC    64               // K chunk (64 fp16 = 128 B row)
#define BM    128
#define BN    64
#define NCTA  128
#define GRPSZ 8

// ---------------- static device scratch ----------------
__device__ __half g_H[2][BATCH * UNITS];          // hidden state, fp16
__device__ __half g_Whh_h[UNITS * UNITS];         // W_hh single fp16 plane, [n][k]
__device__ __half g_WX_h[UNITS * 128];            // W_xh hi plane, [n][k pad 128]
__device__ __half g_WX_l[UNITS * 128];
__device__ float  g_EP[(size_t)NWORDS * UNITS];   // emb @ W_xh + b_h  (fp32)
__device__ unsigned g_flag[NCTA * 32];            // per (grp,col) flags, 128B stride

// ---------------- PTX helpers ----------------
__device__ __forceinline__ uint32_t smem_to_u32(const void* p) {
    uint32_t a;
    asm("{ .reg .u64 t; cvta.to.shared.u64 t, %1; cvt.u32.u64 %0, t; }" : "=r"(a) : "l"(p));
    return a;
}
__device__ __forceinline__ float tanh_fast(float x) {
    float r;
    asm("tanh.approx.f32 %0, %1;" : "=f"(r) : "f"(x));
    return r;
}
#define CP16(dst, src) \
    asm volatile("cp.async.cg.shared.global [%0], [%1], 16;" :: "r"(dst), "l"(src))
#define CP_COMMIT() asm volatile("cp.async.commit_group;" ::: "memory")
#define CP_WAIT(n)  asm volatile("cp.async.wait_group %0;" :: "n"(n) : "memory")

#define LDSM_X4(r0, r1, r2, r3, addr) \
    asm volatile("ldmatrix.sync.aligned.m8n8.x4.shared.b16 {%0,%1,%2,%3}, [%4];" \
                 : "=r"(r0), "=r"(r1), "=r"(r2), "=r"(r3) : "r"(addr))

#define MMAF16(d, a0, a1, a2, a3, b0, b1) \
    asm volatile("mma.sync.aligned.m16n8k16.row.col.f32.f16.f16.f32 " \
                 "{%0,%1,%2,%3}, {%4,%5,%6,%7}, {%8,%9}, {%0,%1,%2,%3};" \
                 : "+f"((d)[0]), "+f"((d)[1]), "+f"((d)[2]), "+f"((d)[3]) \
                 : "r"(a0), "r"(a1), "r"(a2), "r"(a3), "r"(b0), "r"(b1))

#define SWZ(bo) ((bo) ^ (((bo) >> 3) & 0x70))

#define BAR_CTA()  asm volatile("barrier.sync 0;" ::: "memory")
#define BAR_G(id)  asm volatile("barrier.sync %0, 256;" :: "n"(id) : "memory")

// ---------------- SMEM layouts ----------------
// main: B resident 8 chunks x 8KB = 64KB; A 6 bufs x 16KB = 96KB
// stage (g1 partial acc, 128 x 72 fp32 = 36KB) overlays A bufs 3..5.
#define B_RES(c)     ((c) * 8192)
#define A_OFF(buf)   (65536 + (buf) * 16384)
#define STAGE_OFF    A_OFF(3)
#define STG_STRIDE   72
#define SMEM_MAIN    (65536 + 6 * 16384)           // 163840
// proj: A fp16 2 chunks x 16KB = 32KB; B 2 planes x 2 chunks x 8KB = 32KB
#define PA(ch)       ((ch) * 16384)
#define PB(p, ch)    (32768 + ((p) * 2 + (ch)) * 8192)
#define SMEM_PROJ    65536

// ---------------- prep kernels ----------------
__global__ void build_whh_kernel(const float* __restrict__ Whh) {
    int i = blockIdx.x * blockDim.x + threadIdx.x;
    if (i >= UNITS * UNITS) return;
    int n = i / UNITS;
    int k = i - n * UNITS;
    g_Whh_h[i] = __float2half(Whh[(size_t)k * UNITS + n]);
}

__global__ void build_wx_kernel(const float* __restrict__ Wxh) {
    int i = blockIdx.x * blockDim.x + threadIdx.x;
    if (i >= UNITS * 128) return;
    int n = i >> 7;
    int k = i & 127;
    float v = (k < EDIM) ? Wxh[(size_t)k * UNITS + n] : 0.0f;
    __half hi = __float2half(v);
    g_WX_h[i] = hi;
    g_WX_l[i] = __float2half(v - __half2float(hi));
}

__global__ void init_h_kernel() {
    int i = blockIdx.x * blockDim.x + threadIdx.x;
    if (i < NCTA * 32) g_flag[i] = 0u;
    if (i >= BATCH * UNITS) return;
    g_H[0][i] = __float2half(0.0f);
}

// ---------------- table projection: g_EP = emb @ W_xh + b_h (hi/lo, one-shot) ----
__global__ __launch_bounds__(256, 2)
void proj_gemm(const float* __restrict__ emb, const float* __restrict__ bh) {
    extern __shared__ char smem[];
    const uint32_t su = smem_to_u32(smem);
    const int tid = threadIdx.x, wid = tid >> 5, lane = tid & 31;
    const int col0 = blockIdx.x * BN;
    const int r0   = blockIdx.y * BM;

    {
#pragma unroll
        for (int i = 0; i < 8; i++) {
            int u = tid + i * 256;
            int p  = u >> 10;
            int rem = u & 1023;
            int ch = rem >> 9;
            int r  = (rem >> 3) & 63;
            int s  = rem & 7;
            uint32_t so = SWZ((uint32_t)(r * 128 + s * 16));
            const __half* wsrc = (p == 0 ? g_WX_h : g_WX_l) + (size_t)(col0 + r) * 128 + ch * 64;
            CP16(su + PB(p, ch) + so, (const char*)wsrc + s * 16);
        }
    }
    CP_COMMIT();

    {
#pragma unroll
        for (int i = 0; i < 64; i++) {
            int idx = tid + i * 256;
            int r = idx >> 7, k = idx & 127;
            float v = 0.0f;
            if (r0 + r < NWORDS && k < EDIM)
                v = emb[(size_t)(r0 + r) * EDIM + k];
            int ch = k >> 6, kk = k & 63;
            uint32_t so = SWZ((uint32_t)(r * 128 + kk * 2));
            *reinterpret_cast<__half*>(smem + PA(ch) + so) = __float2half(v);
        }
    }
    CP_WAIT(0);
    __syncthreads();

    const int m_base = (wid & 3) * 32;
    const int n_base = (wid >> 2) * 32;
    const int a_row = lane & 15, a_kh = (lane >> 4) * 16;
    const int b_row = ((lane >> 4) << 3) + (lane & 7), b_kh = ((lane >> 3) & 1) * 16;
    const int lg = lane >> 2, tig = lane & 3;

    float acc[2][4][4];
#pragma unroll
    for (int mt = 0; mt < 2; mt++)
#pragma unroll
        for (int nt = 0; nt < 4; nt++)
#pragma unroll
            for (int q = 0; q < 4; q++) acc[mt][nt][q] = 0.0f;

#pragma unroll
    for (int ks = 0; ks < 7; ks++) {
        const int ch = ks >> 2;
        const int kb = (ks & 3) * 32;
        uint32_t A[2][4], Bh[4][2], Bl[4][2];
#pragma unroll
        for (int mt = 0; mt < 2; mt++) {
            uint32_t bo = SWZ((uint32_t)((m_base + mt * 16 + a_row) * 128 + kb + a_kh));
            LDSM_X4(A[mt][0], A[mt][1], A[mt][2], A[mt][3], su + PA(ch) + bo);
        }
#pragma unroll
        for (int np = 0; np < 2; np++) {
            uint32_t bo = SWZ((uint32_t)((n_base + np * 16 + b_row) * 128 + kb + b_kh));
            LDSM_X4(Bh[np * 2][0], Bh[np * 2][1], Bh[np * 2 + 1][0], Bh[np * 2 + 1][1],
                    su + PB(0, ch) + bo);
            LDSM_X4(Bl[np * 2][0], Bl[np * 2][1], Bl[np * 2 + 1][0], Bl[np * 2 + 1][1],
                    su + PB(1, ch) + bo);
        }
#pragma unroll
        for (int mt = 0; mt < 2; mt++)
#pragma unroll
            for (int nt = 0; nt < 4; nt++) {
                MMAF16(acc[mt][nt], A[mt][0], A[mt][1], A[mt][2], A[mt][3],
                       Bh[nt][0], Bh[nt][1]);
                MMAF16(acc[mt][nt], A[mt][0], A[mt][1], A[mt][2], A[mt][3],
                       Bl[nt][0], Bl[nt][1]);
            }
    }

#pragma unroll
    for (int mt = 0; mt < 2; mt++)
#pragma unroll
        for (int nt = 0; nt < 4; nt++) {
            const int col = col0 + n_base + nt * 8 + tig * 2;
            const float b0 = __ldg(bh + col);
            const float b1 = __ldg(bh + col + 1);
#pragma unroll
            for (int half = 0; half < 2; half++) {
                const int row = r0 + m_base + mt * 16 + lg + half * 8;
                if (row < NWORDS) {
                    float2 v;
                    v.x = acc[mt][nt][half * 2] + b0;
                    v.y = acc[mt][nt][half * 2 + 1] + b1;
                    *reinterpret_cast<float2*>(g_EP + (size_t)row * UNITS + col) = v;
                }
            }
        }
}

// ---------------- persistent recurrence: split-K(2), single-plane W ----------------
__global__ __launch_bounds__(512, 1)
void rnn_persistent(const int* __restrict__ inputs) {
    extern __shared__ char smem[];
    const uint32_t su = smem_to_u32(smem);
    const int tid = threadIdx.x, wid = tid >> 5, lane = tid & 31;
    const int kg  = wid >> 3;                      // k-group 0/1
    const int wg  = wid & 7;
    const int tg  = tid & 255;
    const int bid = blockIdx.x;
    const int cidx = bid & 7;
    const int grp  = bid >> 3;
    const int col0 = cidx * BN, row0 = grp * BM;

    // resident B: W_hh single plane, 8 chunks
    {
#pragma unroll
        for (int i = 0; i < 8; i++) {
            int u = tid + i * 512;
            int rg = u >> 3, s = u & 7;
            int ch = rg >> 6, r = rg & 63;
            uint32_t so = SWZ((uint32_t)(r * 128 + s * 16));
            size_t gs = (size_t)(col0 + r) * UNITS + ch * 64;
            CP16(su + B_RES(ch) + so, (const char*)(g_Whh_h + gs) + s * 16);
        }
    }
    CP_COMMIT();
    // prefill A buffer 0 with zeros (H_0 own chunk, forwarded path)
    {
        uint4 z = make_uint4(0, 0, 0, 0);
        reinterpret_cast<uint4*>(smem + A_OFF(0))[tid]       = z;
        reinterpret_cast<uint4*>(smem + A_OFF(0))[tid + 512] = z;
    }
    CP_WAIT(0);
    __syncthreads();

    const int m_base = (wg & 3) * 32;
    const int n_base = (wg >> 2) * 32;
    const int a_row = lane & 15, a_kh = (lane >> 4) * 16;
    const int b_row = ((lane >> 4) << 3) + (lane & 7), b_kh = ((lane >> 3) & 1) * 16;
    const int lg = lane >> 2, tig = lane & 3;

    for (int t = 0; t < TLEN; t++) {
        const __half* __restrict__ Hsrc = g_H[t & 1];

        float acc[2][4][4];
#pragma unroll
        for (int mt = 0; mt < 2; mt++)
#pragma unroll
            for (int nt = 0; nt < 4; nt++)
#pragma unroll
                for (int q = 0; q < 4; q++) acc[mt][nt][q] = 0.0f;

        auto spin = [&](int kc) {
            const unsigned* fp = &g_flag[(grp * 8 + kc) * 32];
            unsigned v;
            do {
                asm volatile("ld.acquire.gpu.u32 %0, [%1];" : "=r"(v) : "l"(fp));
            } while ((int)v < t);
        };
        auto load_A = [&](int kc, int buf) {   // 256 threads of one group
            const __half* sh = Hsrc + (size_t)row0 * UNITS + kc * KC;
#pragma unroll
            for (int i = 0; i < 4; i++) {
                int u = tg + i * 256;
                int r = u >> 3, s = u & 7;
                uint32_t so = SWZ((uint32_t)(r * 128 + s * 16));
                CP16(su + A_OFF(buf) + so, (const char*)(sh + (size_t)r * UNITS) + s * 16);
            }
            CP_COMMIT();
        };

#define PROC_CHUNK(abuf, kc) do {                                             \
            const uint32_t ah_ = su + A_OFF(abuf);                            \
            const uint32_t bh_ = su + B_RES(kc);                              \
            _Pragma("unroll")                                                 \
            for (int ks_ = 0; ks_ < 4; ks_++) {                               \
                const int kb_ = ks_ * 32;                                     \
                uint32_t Af_[2][4], Bh_[4][2];                                \
                _Pragma("unroll")                                             \
                for (int mt_ = 0; mt_ < 2; mt_++) {                           \
                    uint32_t bo = SWZ((uint32_t)((m_base + mt_ * 16 + a_row)  \
                                                 * 128 + kb_ + a_kh));        \
                    LDSM_X4(Af_[mt_][0], Af_[mt_][1], Af_[mt_][2],            \
                            Af_[mt_][3], ah_ + bo);                           \
                }                                                             \
                _Pragma("unroll")                                             \
                for (int np_ = 0; np_ < 2; np_++) {                           \
                    uint32_t bo = SWZ((uint32_t)((n_base + np_ * 16 + b_row)  \
                                                 * 128 + kb_ + b_kh));        \
                    LDSM_X4(Bh_[np_ * 2][0], Bh_[np_ * 2][1],                 \
                            Bh_[np_ * 2 + 1][0], Bh_[np_ * 2 + 1][1],         \
                            bh_ + bo);                                        \
                }                                                             \
                _Pragma("unroll")                                             \
                for (int mt_ = 0; mt_ < 2; mt_++)                             \
                    _Pragma("unroll")                                         \
                    for (int nt_ = 0; nt_ < 4; nt_++)                         \
                        MMAF16(acc[mt_][nt_], Af_[mt_][0], Af_[mt_][1],       \
                               Af_[mt_][2], Af_[mt_][3],                      \
                               Bh_[nt_][0], Bh_[nt_][1]);                     \
            }                                                                 \
        } while (0)

        if (kg == 0) {
            // ---- EP gather into regs (consumed only at epilogue) ----
            float ep[2][4][4];
#pragma unroll
            for (int mt = 0; mt < 2; mt++)
#pragma unroll
                for (int half = 0; half < 2; half++) {
                    const int row = row0 + m_base + mt * 16 + lg + half * 8;
                    const int idx = __ldg(inputs + (size_t)row * TLEN + t);
                    const float* eprow = g_EP + (size_t)idx * UNITS + col0;
#pragma unroll
                    for (int nt = 0; nt < 4; nt++) {
                        float2 v = __ldg(reinterpret_cast<const float2*>(
                                             eprow + n_base + nt * 8 + tig * 2));
                        ep[mt][nt][half * 2]     = v.x;
                        ep[mt][nt][half * 2 + 1] = v.y;
                    }
                }

            const int k1 = (cidx + 1) & 7, k2 = (cidx + 2) & 7, k3 = (cidx + 3) & 7;
            spin(k1); load_A(k1, 1);
            spin(k2); load_A(k2, 2);
            PROC_CHUNK(0, cidx);               // own chunk, smem-forwarded
            CP_WAIT(1); BAR_G(1);              // k1 in; buf0 consumed group-wide
            spin(k3); load_A(k3, 0);
            PROC_CHUNK(1, k1);
            CP_WAIT(1); BAR_G(1);              // k2 in
            PROC_CHUNK(2, k2);
            CP_WAIT(0); BAR_G(1);              // k3 in
            PROC_CHUNK(0, k3);

            BAR_CTA();                          // stage ready (pairs with g1 #1)

            // ---- combine + tanh + store + forward ----
            __half* __restrict__ Hdst = g_H[(t + 1) & 1];
            const float* stg = reinterpret_cast<const float*>(smem + STAGE_OFF);
#pragma unroll
            for (int mt = 0; mt < 2; mt++)
#pragma unroll
                for (int nt = 0; nt < 4; nt++) {
                    const int col_l = n_base + nt * 8 + tig * 2;
                    const int col   = col0 + col_l;
#pragma unroll
                    for (int half = 0; half < 2; half++) {
                        const int row_l = m_base + mt * 16 + lg + half * 8;
                        float2 s2 = *reinterpret_cast<const float2*>(
                                        stg + row_l * STG_STRIDE + col_l);
                        float v0 = tanh_fast(acc[mt][nt][half * 2 + 0] + s2.x
                                             + ep[mt][nt][half * 2 + 0]);
                        float v1 = tanh_fast(acc[mt][nt][half * 2 + 1] + s2.y
                                             + ep[mt][nt][half * 2 + 1]);
                        __half2 hp;
                        hp.x = __float2half(v0);
                        hp.y = __float2half(v1);
                        *reinterpret_cast<__half2*>(
                            Hdst + (size_t)(row0 + row_l) * UNITS + col) = hp;
                        uint32_t so = SWZ((uint32_t)(row_l * 128 + col_l * 2));
                        *reinterpret_cast<__half2*>(smem + A_OFF(0) + so) = hp;
                    }
                }

            BAR_CTA();                          // pairs with g1 #2
            if (tid == 0) {
                __threadfence();
                unsigned* fp = &g_flag[(grp * 8 + cidx) * 32];
                asm volatile("st.release.gpu.u32 [%0], %1;"
                             :: "l"(fp), "r"((unsigned)(t + 1)) : "memory");
            }
        } else {
            const int k4 = (cidx + 4) & 7, k5 = (cidx + 5) & 7;
            const int k6 = (cidx + 6) & 7, k7 = (cidx + 7) & 7;
            spin(k4); load_A(k4, 3);
            spin(k5); load_A(k5, 4);
            spin(k6); load_A(k6, 5);
            CP_WAIT(2); BAR_G(2);              // k4 in
            PROC_CHUNK(3, k4);
            BAR_G(2);                          // buf3 consumed group-wide
            spin(k7); load_A(k7, 3);
            CP_WAIT(2); BAR_G(2);              // k5 in
            PROC_CHUNK(4, k5);
            CP_WAIT(1); BAR_G(2);              // k6 in
            PROC_CHUNK(5, k6);
            CP_WAIT(0); BAR_G(2);              // k7 in
            PROC_CHUNK(3, k7);
            BAR_G(2);                          // buf3 reads done before stage write

            // ---- stage partial acc (overlays bufs 3..5, all consumed) ----
            float* stg = reinterpret_cast<float*>(smem + STAGE_OFF);
#pragma unroll
            for (int mt = 0; mt < 2; mt++)
#pragma unroll
                for (int nt = 0; nt < 4; nt++) {
                    const int col_l = n_base + nt * 8 + tig * 2;
#pragma unroll
                    for (int half = 0; half < 2; half++) {
                        const int row_l = m_base + mt * 16 + lg + half * 8;
                        float2 w;
                        w.x = acc[mt][nt][half * 2 + 0];
                        w.y = acc[mt][nt][half * 2 + 1];
                        *reinterpret_cast<float2*>(
                            stg + row_l * STG_STRIDE + col_l) = w;
                    }
                }
            BAR_CTA();                          // #1: stage visible to g0
            BAR_CTA();                          // #2: g0 done with stage; bufs reusable
        }
#undef PROC_CHUNK
    }
}

// ---------------- final logits ----------------
__global__ __launch_bounds__(256)
void final_logits_kernel(const float* __restrict__ Wout,
                         const float* __restrict__ bout,
                         float* __restrict__ out) {
    const __half* __restrict__ h = g_H[0];   // TLEN = 80 even -> plane 0
    int warp = threadIdx.x >> 5;
    int lane = threadIdx.x & 31;
    int row = blockIdx.x * 8 + warp;
    if (row >= BATCH) return;
    float s = 0.0f;
#pragma unroll
    for (int j = 0; j < UNITS / 32; j++) {
        int k = lane + j * 32;
        s += __half2float(h[(size_t)row * UNITS + k]) * Wout[k];
    }
#pragma unroll
    for (int o = 16; o; o >>= 1) s += __shfl_xor_sync(0xffffffff, s, o);
    if (lane == 0) out[row] = 1.0f / (1.0f + expf(-(s + bout[0])));
}

// ---------------- launch ----------------
extern "C" void kernel_launch(void* const* d_in, const int* in_sizes, int n_in,
                              void* d_out, int out_size) {
    const int*   inputs = (const int*)  d_in[0];
    const float* emb    = (const float*)d_in[1];
    const float* Wxh    = (const float*)d_in[2];
    const float* Whh    = (const float*)d_in[3];
    const float* bh     = (const float*)d_in[4];
    const float* Wout   = (const float*)d_in[5];
    const float* bout   = (const float*)d_in[6];
    float* out = (float*)d_out;

    cudaFuncSetAttribute(rnn_persistent,
                         cudaFuncAttributeMaxDynamicSharedMemorySize, SMEM_MAIN);
    cudaFuncSetAttribute(proj_gemm,
                         cudaFuncAttributeMaxDynamicSharedMemorySize, SMEM_PROJ);

    build_whh_kernel<<<(UNITS * UNITS + 255) / 256, 256>>>(Whh);
    build_wx_kernel<<<(UNITS * 128 + 255) / 256, 256>>>(Wxh);
    init_h_kernel<<<(BATCH * UNITS + 255) / 256, 256>>>();

    dim3 gp(UNITS / BN, (NWORDS + BM - 1) / BM);   // (8, 274)
    proj_gemm<<<gp, 256, SMEM_PROJ>>>(emb, bh);

    rnn_persistent<<<NCTA, 512, SMEM_MAIN>>>(inputs);

    final_logits_kernel<<<BATCH / 8, 256>>>(Wout, bout, out);
}